// round 1
// baseline (speedup 1.0000x reference)
#include <cuda_runtime.h>

#define BATCH   1024
#define NCOL    64
#define NCOND   64
#define NRODT   1024
#define NEST    128
#define NFOREST 100
#define NHID    128
#define NCLASS  10
#define EPSF    1e-5f
#define TB      8
#define ROWS_PER_BLOCK 64

// Scratch (static device allocations are allowed; cudaMalloc is not)
__device__ float g_W[BATCH * NRODT];                 // rODT scores w  (4 MB)
__device__ float g_Y[(size_t)BATCH * NFOREST * NCLASS]; // per-forest logits (4 MB)

// ---------------------------------------------------------------------------
// Kernel 1: fused ConditionGeneration -> permute -> GN -> 4x4 conv -> ReLU
//           -> GN -> 4-dot  => w[b, g]
// One thread per (batch b, rODT g).
// ---------------------------------------------------------------------------
__global__ void cond_kernel(
    const float* __restrict__ x,    const float* __restrict__ w1,
    const float* __restrict__ b1,   const int*   __restrict__ perm,
    const float* __restrict__ gn1g, const float* __restrict__ gn1b,
    const float* __restrict__ w2a,  const float* __restrict__ b2a,
    const float* __restrict__ gn2g, const float* __restrict__ gn2b,
    const float* __restrict__ w2b,  const float* __restrict__ b2b)
{
    __shared__ float xs[NCOL];
    const int b = blockIdx.y;
    const int t = threadIdx.x;
    if (t < NCOL) xs[t] = x[b * NCOL + t];
    __syncthreads();

    const int g = blockIdx.x * 256 + t;
    const int base = g * 4;

    // 4 permuted conditions for this rODT
    const int4 p4 = ((const int4*)perm)[g];
    const int pv[4] = {p4.x, p4.y, p4.z, p4.w};
    float o[4];
#pragma unroll
    for (int i = 0; i < 4; i++) {
        const int p = pv[i];
        const int col = p & 63;          // permuted flat idx = cond*64 + col
        const int cond = p >> 6;
        const int wi = col * NCOND + cond;  // w1/b1 flat index (NCOL, NCOND)
        const float tv = fmaf(xs[col], w1[wi], b1[wi]);
        o[i] = 1.f / (1.f + __expf(-tv));
    }

    // GroupNorm 1 (group of 4, biased var)
    float mu = 0.f, s2 = 0.f;
#pragma unroll
    for (int i = 0; i < 4; i++) { mu += o[i]; s2 += o[i] * o[i]; }
    mu *= 0.25f;
    s2 = s2 * 0.25f - mu * mu;
    const float rstd = rsqrtf(s2 + EPSF);
    const float4 g1  = ((const float4*)gn1g)[g];
    const float4 be1 = ((const float4*)gn1b)[g];
    float hn[4];
    hn[0] = (o[0] - mu) * rstd * g1.x + be1.x;
    hn[1] = (o[1] - mu) * rstd * g1.y + be1.y;
    hn[2] = (o[2] - mu) * rstd * g1.z + be1.z;
    hn[3] = (o[3] - mu) * rstd * g1.w + be1.w;

    // grouped 4x4 conv + bias + ReLU
    const float4 bb2 = ((const float4*)b2a)[g];
    float h2[4] = {bb2.x, bb2.y, bb2.z, bb2.w};
#pragma unroll
    for (int i = 0; i < 4; i++) {
        const float4 wr = ((const float4*)w2a)[g * 4 + i];  // w2a[g, i, 0..3]
        h2[0] = fmaf(hn[i], wr.x, h2[0]);
        h2[1] = fmaf(hn[i], wr.y, h2[1]);
        h2[2] = fmaf(hn[i], wr.z, h2[2]);
        h2[3] = fmaf(hn[i], wr.w, h2[3]);
    }
#pragma unroll
    for (int i = 0; i < 4; i++) h2[i] = fmaxf(h2[i], 0.f);

    // GroupNorm 2
    float mu2 = 0.f, t2 = 0.f;
#pragma unroll
    for (int i = 0; i < 4; i++) { mu2 += h2[i]; t2 += h2[i] * h2[i]; }
    mu2 *= 0.25f;
    t2 = t2 * 0.25f - mu2 * mu2;
    const float rstd2 = rsqrtf(t2 + EPSF);
    const float4 g2  = ((const float4*)gn2g)[g];
    const float4 be2 = ((const float4*)gn2b)[g];
    const float4 wb  = ((const float4*)w2b)[g];   // w2b[g, 0..3, 0]

    float wv = b2b[g];
    wv = fmaf((h2[0] - mu2) * rstd2 * g2.x + be2.x, wb.x, wv);
    wv = fmaf((h2[1] - mu2) * rstd2 * g2.y + be2.y, wb.y, wv);
    wv = fmaf((h2[2] - mu2) * rstd2 * g2.z + be2.z, wb.z, wv);
    wv = fmaf((h2[3] - mu2) * rstd2 * g2.w + be2.w, wb.w, wv);

    g_W[b * NRODT + g] = wv;
}

// ---------------------------------------------------------------------------
// Kernel 2: per (64-batch-row tile, forest): gather+softmax -> F = ws @ Es[f]
//           -> LN -> lin1+ReLU -> LN -> lin2 ; writes per-forest logits.
// 128 threads, thread t = hidden channel t. Register-blocked over TB=8 rows.
// Es[f] (64KB) and lin1_w (64KB) live in dynamic shared.
// ---------------------------------------------------------------------------
__global__ void forest_kernel(
    const float* __restrict__ E,     const int*   __restrict__ swr,
    const float* __restrict__ ln1g,  const float* __restrict__ ln1b,
    const float* __restrict__ lin1w, const float* __restrict__ lin1b,
    const float* __restrict__ ln2g,  const float* __restrict__ ln2b,
    const float* __restrict__ lin2w, const float* __restrict__ lin2b)
{
    extern __shared__ __align__(16) float sm[];
    float* Es = sm;                 // [NEST][NHID]
    float* L1 = sm + NEST * NHID;   // [NHID][NHID]
    __shared__ __align__(16) float L2w[NHID * NCLASS];
    __shared__ int idx[NEST];
    __shared__ __align__(16) float ws_s[NEST * TB];  // [e][r]
    __shared__ __align__(16) float zn_s[NHID * TB];  // [k][r]
    __shared__ float rsumA[TB * 4], rsumB[TB * 4];

    const int t = threadIdx.x;        // 0..127
    const int lane = t & 31, wid = t >> 5;
    const int f = blockIdx.y;
    const int b0 = blockIdx.x * ROWS_PER_BLOCK;

    idx[t] = swr[f * NEST + t];
    __syncthreads();

    // Gather Es[f] rows (coalesced float4 per warp-row)
    for (int e = wid; e < NEST; e += 4)
        ((float4*)(Es + e * NHID))[lane] =
            ((const float4*)(E + (size_t)idx[e] * NHID))[lane];
    // lin1_w and lin2_w into shared
    for (int i = t; i < NHID * NHID / 4; i += 128)
        ((float4*)L1)[i] = ((const float4*)lin1w)[i];
    for (int i = t; i < NHID * NCLASS; i += 128) L2w[i] = lin2w[i];

    const float l1g = ln1g[t], l1bv = ln1b[t];
    const float l2gv = ln2g[t], l2bv = ln2b[t];
    const float lb1 = lin1b[t];
    const int myidx = idx[t];
    __syncthreads();

    for (int ch = 0; ch < ROWS_PER_BLOCK / TB; ch++) {
        const int bb = b0 + ch * TB;

        // ---- softmax over estimators (thread t = estimator t), 8 rows ----
        float v[TB], ev[TB];
#pragma unroll
        for (int r = 0; r < TB; r++)
            v[r] = g_W[(size_t)(bb + r) * NRODT + myidx];
#pragma unroll
        for (int r = 0; r < TB; r++) {
            float m = v[r];
            for (int o = 16; o > 0; o >>= 1)
                m = fmaxf(m, __shfl_xor_sync(0xffffffffu, m, o));
            if (lane == 0) rsumA[r * 4 + wid] = m;
        }
        __syncthreads();
#pragma unroll
        for (int r = 0; r < TB; r++) {
            const float m = fmaxf(fmaxf(rsumA[r * 4], rsumA[r * 4 + 1]),
                                  fmaxf(rsumA[r * 4 + 2], rsumA[r * 4 + 3]));
            ev[r] = __expf(v[r] - m);
            float s = ev[r];
            for (int o = 16; o > 0; o >>= 1)
                s += __shfl_xor_sync(0xffffffffu, s, o);
            if (lane == 0) rsumB[r * 4 + wid] = s;
        }
        __syncthreads();
#pragma unroll
        for (int r = 0; r < TB; r++) {
            const float s = rsumB[r * 4] + rsumB[r * 4 + 1] +
                            rsumB[r * 4 + 2] + rsumB[r * 4 + 3];
            ws_s[t * TB + r] = ev[r] * (1.f / s);
        }
        __syncthreads();

        // ---- F[r][t] = sum_e ws[r][e] * Es[e][t] ----
        float acc[TB];
#pragma unroll
        for (int r = 0; r < TB; r++) acc[r] = 0.f;
#pragma unroll 4
        for (int e = 0; e < NEST; e++) {
            const float es = Es[e * NHID + t];
            const float4 wa = *(const float4*)(ws_s + e * TB);
            const float4 wb = *(const float4*)(ws_s + e * TB + 4);
            acc[0] = fmaf(wa.x, es, acc[0]);
            acc[1] = fmaf(wa.y, es, acc[1]);
            acc[2] = fmaf(wa.z, es, acc[2]);
            acc[3] = fmaf(wa.w, es, acc[3]);
            acc[4] = fmaf(wb.x, es, acc[4]);
            acc[5] = fmaf(wb.y, es, acc[5]);
            acc[6] = fmaf(wb.z, es, acc[6]);
            acc[7] = fmaf(wb.w, es, acc[7]);
        }

        // ---- LayerNorm 1 ----
#pragma unroll
        for (int r = 0; r < TB; r++) {
            float s = acc[r], s2 = acc[r] * acc[r];
            for (int o = 16; o > 0; o >>= 1) {
                s  += __shfl_xor_sync(0xffffffffu, s, o);
                s2 += __shfl_xor_sync(0xffffffffu, s2, o);
            }
            if (lane == 0) { rsumA[r * 4 + wid] = s; rsumB[r * 4 + wid] = s2; }
        }
        __syncthreads();
#pragma unroll
        for (int r = 0; r < TB; r++) {
            const float m = (rsumA[r * 4] + rsumA[r * 4 + 1] +
                             rsumA[r * 4 + 2] + rsumA[r * 4 + 3]) * (1.f / NHID);
            const float va = (rsumB[r * 4] + rsumB[r * 4 + 1] +
                              rsumB[r * 4 + 2] + rsumB[r * 4 + 3]) * (1.f / NHID) - m * m;
            const float rstd = rsqrtf(va + EPSF);
            zn_s[t * TB + r] = (acc[r] - m) * rstd * l1g + l1bv;
        }
        __syncthreads();

        // ---- lin1 + ReLU ----
#pragma unroll
        for (int r = 0; r < TB; r++) acc[r] = lb1;
#pragma unroll 4
        for (int k = 0; k < NHID; k++) {
            const float l = L1[k * NHID + t];
            const float4 za = *(const float4*)(zn_s + k * TB);
            const float4 zb = *(const float4*)(zn_s + k * TB + 4);
            acc[0] = fmaf(za.x, l, acc[0]);
            acc[1] = fmaf(za.y, l, acc[1]);
            acc[2] = fmaf(za.z, l, acc[2]);
            acc[3] = fmaf(za.w, l, acc[3]);
            acc[4] = fmaf(zb.x, l, acc[4]);
            acc[5] = fmaf(zb.y, l, acc[5]);
            acc[6] = fmaf(zb.z, l, acc[6]);
            acc[7] = fmaf(zb.w, l, acc[7]);
        }
#pragma unroll
        for (int r = 0; r < TB; r++) acc[r] = fmaxf(acc[r], 0.f);

        // ---- LayerNorm 2 ----
#pragma unroll
        for (int r = 0; r < TB; r++) {
            float s = acc[r], s2 = acc[r] * acc[r];
            for (int o = 16; o > 0; o >>= 1) {
                s  += __shfl_xor_sync(0xffffffffu, s, o);
                s2 += __shfl_xor_sync(0xffffffffu, s2, o);
            }
            if (lane == 0) { rsumA[r * 4 + wid] = s; rsumB[r * 4 + wid] = s2; }
        }
        __syncthreads();   // also guards zn_s overwrite vs lin1-loop readers
#pragma unroll
        for (int r = 0; r < TB; r++) {
            const float m = (rsumA[r * 4] + rsumA[r * 4 + 1] +
                             rsumA[r * 4 + 2] + rsumA[r * 4 + 3]) * (1.f / NHID);
            const float va = (rsumB[r * 4] + rsumB[r * 4 + 1] +
                              rsumB[r * 4 + 2] + rsumB[r * 4 + 3]) * (1.f / NHID) - m * m;
            const float rstd = rsqrtf(va + EPSF);
            zn_s[t * TB + r] = (acc[r] - m) * rstd * l2gv + l2bv;
        }
        __syncthreads();

        // ---- lin2 (128 -> 10), 80 active threads: r = t%8, c = t/8 ----
        if (t < TB * NCLASS) {
            const int r = t & (TB - 1);
            const int c = t >> 3;
            float y = lin2b[c];
#pragma unroll 4
            for (int k = 0; k < NHID; k++)
                y = fmaf(zn_s[k * TB + r], L2w[k * NCLASS + c], y);
            g_Y[((size_t)(bb + r) * NFOREST + f) * NCLASS + c] = y;
        }
        __syncthreads();   // before next chunk reuses ws_s/rsum
    }
}

// ---------------------------------------------------------------------------
// Kernel 3: deterministic mean over forests
// ---------------------------------------------------------------------------
__global__ void mean_kernel(float* __restrict__ out)
{
    const int i = blockIdx.x * 256 + threadIdx.x;
    if (i >= BATCH * NCLASS) return;
    const int b = i / NCLASS;
    const int c = i - b * NCLASS;
    const float* p = g_Y + (size_t)b * NFOREST * NCLASS + c;
    float s = 0.f;
#pragma unroll 4
    for (int f = 0; f < NFOREST; f++) s += p[f * NCLASS];
    out[i] = s * (1.f / NFOREST);
}

// ---------------------------------------------------------------------------
extern "C" void kernel_launch(void* const* d_in, const int* in_sizes, int n_in,
                              void* d_out, int out_size)
{
    const float* x     = (const float*)d_in[0];
    const float* w1    = (const float*)d_in[1];
    const float* b1    = (const float*)d_in[2];
    const int*   perm  = (const int*)  d_in[3];
    const float* gn1g  = (const float*)d_in[4];
    const float* gn1b  = (const float*)d_in[5];
    const float* w2a   = (const float*)d_in[6];
    const float* b2a   = (const float*)d_in[7];
    const float* gn2g  = (const float*)d_in[8];
    const float* gn2b  = (const float*)d_in[9];
    const float* w2b   = (const float*)d_in[10];
    const float* b2b   = (const float*)d_in[11];
    const float* E     = (const float*)d_in[12];
    const int*   swr   = (const int*)  d_in[13];
    const float* ln1g  = (const float*)d_in[14];
    const float* ln1b  = (const float*)d_in[15];
    const float* lin1w = (const float*)d_in[16];
    const float* lin1b = (const float*)d_in[17];
    const float* ln2g  = (const float*)d_in[18];
    const float* ln2b  = (const float*)d_in[19];
    const float* lin2w = (const float*)d_in[20];
    const float* lin2b = (const float*)d_in[21];

    const int dyn_smem = 2 * NEST * NHID * (int)sizeof(float);  // 128 KB
    cudaFuncSetAttribute(forest_kernel,
                         cudaFuncAttributeMaxDynamicSharedMemorySize, dyn_smem);

    cond_kernel<<<dim3(NRODT / 256, BATCH), 256>>>(
        x, w1, b1, perm, gn1g, gn1b, w2a, b2a, gn2g, gn2b, w2b, b2b);

    forest_kernel<<<dim3(BATCH / ROWS_PER_BLOCK, NFOREST), 128, dyn_smem>>>(
        E, swr, ln1g, ln1b, lin1w, lin1b, ln2g, ln2b, lin2w, lin2b);

    mean_kernel<<<(BATCH * NCLASS + 255) / 256, 256>>>((float*)d_out);
}

// round 2
// speedup vs baseline: 1.9838x; 1.9838x over previous
#include <cuda_runtime.h>

#define BATCH   1024
#define NCOL    64
#define NCOND   64
#define NRODT   1024
#define NEST    128
#define NFOREST 100
#define NHID    128
#define NCLASS  10
#define EPSF    1e-5f
#define TB      16
#define ROWS_PER_TEAM  32
#define ROWS_PER_BLOCK 64   // 2 teams x 32 rows

// Scratch (static device allocations are allowed; cudaMalloc is not)
__device__ float g_W[BATCH * NRODT];                    // rODT scores w (4 MB)
__device__ float g_Y[(size_t)BATCH * NFOREST * NCLASS]; // per-forest logits (4 MB)

// ---------------------------------------------------------------------------
// Kernel 1: fused ConditionGeneration -> permute -> GN -> 4x4 conv -> ReLU
//           -> GN -> 4-dot  => w[b, g].  One thread per (batch b, rODT g).
// ---------------------------------------------------------------------------
__global__ void cond_kernel(
    const float* __restrict__ x,    const float* __restrict__ w1,
    const float* __restrict__ b1,   const int*   __restrict__ perm,
    const float* __restrict__ gn1g, const float* __restrict__ gn1b,
    const float* __restrict__ w2a,  const float* __restrict__ b2a,
    const float* __restrict__ gn2g, const float* __restrict__ gn2b,
    const float* __restrict__ w2b,  const float* __restrict__ b2b)
{
    __shared__ float xs[NCOL];
    const int b = blockIdx.y;
    const int t = threadIdx.x;
    if (t < NCOL) xs[t] = x[b * NCOL + t];
    __syncthreads();

    const int g = blockIdx.x * 256 + t;

    const int4 p4 = ((const int4*)perm)[g];
    const int pv[4] = {p4.x, p4.y, p4.z, p4.w};
    float o[4];
#pragma unroll
    for (int i = 0; i < 4; i++) {
        const int p = pv[i];
        const int col = p & 63;             // permuted flat idx = cond*64 + col
        const int cond = p >> 6;
        const int wi = col * NCOND + cond;  // w1/b1 flat index (NCOL, NCOND)
        const float tv = fmaf(xs[col], w1[wi], b1[wi]);
        o[i] = 1.f / (1.f + __expf(-tv));
    }

    float mu = 0.f, s2 = 0.f;
#pragma unroll
    for (int i = 0; i < 4; i++) { mu += o[i]; s2 += o[i] * o[i]; }
    mu *= 0.25f;
    s2 = s2 * 0.25f - mu * mu;
    const float rstd = rsqrtf(s2 + EPSF);
    const float4 g1  = ((const float4*)gn1g)[g];
    const float4 be1 = ((const float4*)gn1b)[g];
    float hn[4];
    hn[0] = (o[0] - mu) * rstd * g1.x + be1.x;
    hn[1] = (o[1] - mu) * rstd * g1.y + be1.y;
    hn[2] = (o[2] - mu) * rstd * g1.z + be1.z;
    hn[3] = (o[3] - mu) * rstd * g1.w + be1.w;

    const float4 bb2 = ((const float4*)b2a)[g];
    float h2[4] = {bb2.x, bb2.y, bb2.z, bb2.w};
#pragma unroll
    for (int i = 0; i < 4; i++) {
        const float4 wr = ((const float4*)w2a)[g * 4 + i];
        h2[0] = fmaf(hn[i], wr.x, h2[0]);
        h2[1] = fmaf(hn[i], wr.y, h2[1]);
        h2[2] = fmaf(hn[i], wr.z, h2[2]);
        h2[3] = fmaf(hn[i], wr.w, h2[3]);
    }
#pragma unroll
    for (int i = 0; i < 4; i++) h2[i] = fmaxf(h2[i], 0.f);

    float mu2 = 0.f, t2 = 0.f;
#pragma unroll
    for (int i = 0; i < 4; i++) { mu2 += h2[i]; t2 += h2[i] * h2[i]; }
    mu2 *= 0.25f;
    t2 = t2 * 0.25f - mu2 * mu2;
    const float rstd2 = rsqrtf(t2 + EPSF);
    const float4 g2  = ((const float4*)gn2g)[g];
    const float4 be2 = ((const float4*)gn2b)[g];
    const float4 wb  = ((const float4*)w2b)[g];

    float wv = b2b[g];
    wv = fmaf((h2[0] - mu2) * rstd2 * g2.x + be2.x, wb.x, wv);
    wv = fmaf((h2[1] - mu2) * rstd2 * g2.y + be2.y, wb.y, wv);
    wv = fmaf((h2[2] - mu2) * rstd2 * g2.z + be2.z, wb.z, wv);
    wv = fmaf((h2[3] - mu2) * rstd2 * g2.w + be2.w, wb.w, wv);

    g_W[b * NRODT + g] = wv;
}

// ---------------------------------------------------------------------------
// Kernel 2: per (64-row tile, forest): softmax -> F = ws @ Es[f] -> LN ->
//           lin1 + ReLU -> LN -> lin2 ; per-forest logits to scratch.
// 256 threads = 2 teams of 128 (team handles its own 32 rows); Es[f] and
// lin1_w shared read-only between teams in dynamic smem. TB=16 register rows.
// ---------------------------------------------------------------------------
__global__ void __launch_bounds__(256, 1) forest_kernel(
    const float* __restrict__ E,     const int*   __restrict__ swr,
    const float* __restrict__ ln1g,  const float* __restrict__ ln1b,
    const float* __restrict__ lin1w, const float* __restrict__ lin1b,
    const float* __restrict__ ln2g,  const float* __restrict__ ln2b,
    const float* __restrict__ lin2w, const float* __restrict__ lin2b)
{
    extern __shared__ __align__(16) float sm[];
    float* Es = sm;                 // [NEST][NHID]  64 KB
    float* L1 = sm + NEST * NHID;   // [NHID][NHID]  64 KB
    __shared__ __align__(16) float L2w[NHID * NCLASS];
    __shared__ int idx[NEST];
    __shared__ __align__(16) float ws_s[2][NEST * TB];  // [team][e][r]
    __shared__ __align__(16) float zn_s[2][NHID * TB];  // [team][k][r]
    __shared__ float rsA[2][TB * 4], rsB[2][TB * 4];

    const int t    = threadIdx.x;       // 0..255
    const int team = t >> 7;            // 0,1
    const int tt   = t & 127;           // within team: channel / estimator id
    const int lane = t & 31;
    const int wid  = tt >> 5;           // warp within team 0..3
    const int f    = blockIdx.y;
    const int b0   = blockIdx.x * ROWS_PER_BLOCK + team * ROWS_PER_TEAM;

    if (t < NEST) idx[t] = swr[f * NEST + t];
    __syncthreads();

    // Gather Es[f] rows (coalesced float4, 8 warps)
    for (int e = (t >> 5); e < NEST; e += 8)
        ((float4*)(Es + e * NHID))[lane] =
            ((const float4*)(E + (size_t)idx[e] * NHID))[lane];
    // lin1_w, lin2_w into shared
    for (int i = t; i < NHID * NHID / 4; i += 256)
        ((float4*)L1)[i] = ((const float4*)lin1w)[i];
    for (int i = t; i < NHID * NCLASS; i += 256) L2w[i] = lin2w[i];

    const float l1g = ln1g[tt], l1bv = ln1b[tt];
    const float l2gv = ln2g[tt], l2bv = ln2b[tt];
    const float lb1 = lin1b[tt];
    const int myidx = idx[tt];
    float* const wsp = ws_s[team];
    float* const znp = zn_s[team];
    float* const rA  = rsA[team];
    float* const rB  = rsB[team];
    __syncthreads();

    for (int ch = 0; ch < ROWS_PER_TEAM / TB; ch++) {
        const int bb = b0 + ch * TB;

        // ---- softmax over estimators (thread tt = estimator), TB rows ----
        float v[TB], ev[TB];
#pragma unroll
        for (int r = 0; r < TB; r++)
            v[r] = g_W[(size_t)(bb + r) * NRODT + myidx];
#pragma unroll
        for (int r = 0; r < TB; r++) {
            float m = v[r];
            for (int o = 16; o > 0; o >>= 1)
                m = fmaxf(m, __shfl_xor_sync(0xffffffffu, m, o));
            if (lane == 0) rA[r * 4 + wid] = m;
        }
        __syncthreads();
#pragma unroll
        for (int r = 0; r < TB; r++) {
            const float m = fmaxf(fmaxf(rA[r * 4], rA[r * 4 + 1]),
                                  fmaxf(rA[r * 4 + 2], rA[r * 4 + 3]));
            ev[r] = __expf(v[r] - m);
            float s = ev[r];
            for (int o = 16; o > 0; o >>= 1)
                s += __shfl_xor_sync(0xffffffffu, s, o);
            if (lane == 0) rB[r * 4 + wid] = s;
        }
        __syncthreads();
#pragma unroll
        for (int r = 0; r < TB; r++) {
            const float s = rB[r * 4] + rB[r * 4 + 1] +
                            rB[r * 4 + 2] + rB[r * 4 + 3];
            wsp[tt * TB + r] = ev[r] * (1.f / s);
        }
        __syncthreads();

        // ---- F[r][tt] = sum_e ws[r][e] * Es[e][tt] ----
        float acc[TB];
#pragma unroll
        for (int r = 0; r < TB; r++) acc[r] = 0.f;
#pragma unroll 4
        for (int e = 0; e < NEST; e++) {
            const float es = Es[e * NHID + tt];
            const float4* wp = (const float4*)(wsp + e * TB);
            const float4 wa = wp[0], wb = wp[1], wc = wp[2], wd = wp[3];
            acc[0]  = fmaf(wa.x, es, acc[0]);
            acc[1]  = fmaf(wa.y, es, acc[1]);
            acc[2]  = fmaf(wa.z, es, acc[2]);
            acc[3]  = fmaf(wa.w, es, acc[3]);
            acc[4]  = fmaf(wb.x, es, acc[4]);
            acc[5]  = fmaf(wb.y, es, acc[5]);
            acc[6]  = fmaf(wb.z, es, acc[6]);
            acc[7]  = fmaf(wb.w, es, acc[7]);
            acc[8]  = fmaf(wc.x, es, acc[8]);
            acc[9]  = fmaf(wc.y, es, acc[9]);
            acc[10] = fmaf(wc.z, es, acc[10]);
            acc[11] = fmaf(wc.w, es, acc[11]);
            acc[12] = fmaf(wd.x, es, acc[12]);
            acc[13] = fmaf(wd.y, es, acc[13]);
            acc[14] = fmaf(wd.z, es, acc[14]);
            acc[15] = fmaf(wd.w, es, acc[15]);
        }

        // ---- LayerNorm 1 ----
#pragma unroll
        for (int r = 0; r < TB; r++) {
            float s = acc[r], s2 = acc[r] * acc[r];
            for (int o = 16; o > 0; o >>= 1) {
                s  += __shfl_xor_sync(0xffffffffu, s, o);
                s2 += __shfl_xor_sync(0xffffffffu, s2, o);
            }
            if (lane == 0) { rA[r * 4 + wid] = s; rB[r * 4 + wid] = s2; }
        }
        __syncthreads();
#pragma unroll
        for (int r = 0; r < TB; r++) {
            const float m = (rA[r * 4] + rA[r * 4 + 1] +
                             rA[r * 4 + 2] + rA[r * 4 + 3]) * (1.f / NHID);
            const float va = (rB[r * 4] + rB[r * 4 + 1] +
                              rB[r * 4 + 2] + rB[r * 4 + 3]) * (1.f / NHID) - m * m;
            const float rstd = rsqrtf(va + EPSF);
            znp[tt * TB + r] = (acc[r] - m) * rstd * l1g + l1bv;
        }
        __syncthreads();

        // ---- lin1 + ReLU ----
#pragma unroll
        for (int r = 0; r < TB; r++) acc[r] = lb1;
#pragma unroll 4
        for (int k = 0; k < NHID; k++) {
            const float l = L1[k * NHID + tt];
            const float4* zp = (const float4*)(znp + k * TB);
            const float4 za = zp[0], zb = zp[1], zc = zp[2], zd = zp[3];
            acc[0]  = fmaf(za.x, l, acc[0]);
            acc[1]  = fmaf(za.y, l, acc[1]);
            acc[2]  = fmaf(za.z, l, acc[2]);
            acc[3]  = fmaf(za.w, l, acc[3]);
            acc[4]  = fmaf(zb.x, l, acc[4]);
            acc[5]  = fmaf(zb.y, l, acc[5]);
            acc[6]  = fmaf(zb.z, l, acc[6]);
            acc[7]  = fmaf(zb.w, l, acc[7]);
            acc[8]  = fmaf(zc.x, l, acc[8]);
            acc[9]  = fmaf(zc.y, l, acc[9]);
            acc[10] = fmaf(zc.z, l, acc[10]);
            acc[11] = fmaf(zc.w, l, acc[11]);
            acc[12] = fmaf(zd.x, l, acc[12]);
            acc[13] = fmaf(zd.y, l, acc[13]);
            acc[14] = fmaf(zd.z, l, acc[14]);
            acc[15] = fmaf(zd.w, l, acc[15]);
        }
#pragma unroll
        for (int r = 0; r < TB; r++) acc[r] = fmaxf(acc[r], 0.f);

        // ---- LayerNorm 2 ----
#pragma unroll
        for (int r = 0; r < TB; r++) {
            float s = acc[r], s2 = acc[r] * acc[r];
            for (int o = 16; o > 0; o >>= 1) {
                s  += __shfl_xor_sync(0xffffffffu, s, o);
                s2 += __shfl_xor_sync(0xffffffffu, s2, o);
            }
            if (lane == 0) { rA[r * 4 + wid] = s; rB[r * 4 + wid] = s2; }
        }
        __syncthreads();   // also guards znp overwrite vs lin1 readers
#pragma unroll
        for (int r = 0; r < TB; r++) {
            const float m = (rA[r * 4] + rA[r * 4 + 1] +
                             rA[r * 4 + 2] + rA[r * 4 + 3]) * (1.f / NHID);
            const float va = (rB[r * 4] + rB[r * 4 + 1] +
                              rB[r * 4 + 2] + rB[r * 4 + 3]) * (1.f / NHID) - m * m;
            const float rstd = rsqrtf(va + EPSF);
            znp[tt * TB + r] = (acc[r] - m) * rstd * l2gv + l2bv;
        }
        __syncthreads();

        // ---- lin2 (128 -> 10): 160 (r,c) items over 128 team threads ----
        for (int it = tt; it < TB * NCLASS; it += 128) {
            const int r = it & (TB - 1);
            const int c = it >> 4;
            float y = lin2b[c];
#pragma unroll 4
            for (int k = 0; k < NHID; k++)
                y = fmaf(znp[k * TB + r], L2w[k * NCLASS + c], y);
            g_Y[((size_t)(bb + r) * NFOREST + f) * NCLASS + c] = y;
        }
        __syncthreads();   // before next chunk reuses wsp/rs
    }
}

// ---------------------------------------------------------------------------
// Kernel 3: deterministic mean over forests
// ---------------------------------------------------------------------------
__global__ void mean_kernel(float* __restrict__ out)
{
    const int i = blockIdx.x * 256 + threadIdx.x;
    if (i >= BATCH * NCLASS) return;
    const int b = i / NCLASS;
    const int c = i - b * NCLASS;
    const float* p = g_Y + (size_t)b * NFOREST * NCLASS + c;
    float s = 0.f;
#pragma unroll 4
    for (int f = 0; f < NFOREST; f++) s += p[f * NCLASS];
    out[i] = s * (1.f / NFOREST);
}

// ---------------------------------------------------------------------------
extern "C" void kernel_launch(void* const* d_in, const int* in_sizes, int n_in,
                              void* d_out, int out_size)
{
    const float* x     = (const float*)d_in[0];
    const float* w1    = (const float*)d_in[1];
    const float* b1    = (const float*)d_in[2];
    const int*   perm  = (const int*)  d_in[3];
    const float* gn1g  = (const float*)d_in[4];
    const float* gn1b  = (const float*)d_in[5];
    const float* w2a   = (const float*)d_in[6];
    const float* b2a   = (const float*)d_in[7];
    const float* gn2g  = (const float*)d_in[8];
    const float* gn2b  = (const float*)d_in[9];
    const float* w2b   = (const float*)d_in[10];
    const float* b2b   = (const float*)d_in[11];
    const float* E     = (const float*)d_in[12];
    const int*   swr   = (const int*)  d_in[13];
    const float* ln1g  = (const float*)d_in[14];
    const float* ln1b  = (const float*)d_in[15];
    const float* lin1w = (const float*)d_in[16];
    const float* lin1b = (const float*)d_in[17];
    const float* ln2g  = (const float*)d_in[18];
    const float* ln2b  = (const float*)d_in[19];
    const float* lin2w = (const float*)d_in[20];
    const float* lin2b = (const float*)d_in[21];

    const int dyn_smem = 2 * NEST * NHID * (int)sizeof(float);  // 128 KB
    cudaFuncSetAttribute(forest_kernel,
                         cudaFuncAttributeMaxDynamicSharedMemorySize, dyn_smem);

    cond_kernel<<<dim3(NRODT / 256, BATCH), 256>>>(
        x, w1, b1, perm, gn1g, gn1b, w2a, b2a, gn2g, gn2b, w2b, b2b);

    forest_kernel<<<dim3(BATCH / ROWS_PER_BLOCK, NFOREST), 256, dyn_smem>>>(
        E, swr, ln1g, ln1b, lin1w, lin1b, ln2g, ln2b, lin2w, lin2b);

    mean_kernel<<<(BATCH * NCLASS + 255) / 256, 256>>>((float*)d_out);
}

// round 3
// speedup vs baseline: 2.4247x; 1.2223x over previous
#include <cuda_runtime.h>

#define BATCH   1024
#define NCOL    64
#define NCOND   64
#define NRODT   1024
#define NEST    128
#define NFOREST 100
#define NHID    128
#define NCLASS  10
#define EPSF    1e-5f
#define TB      16
#define ROWS_PER_TEAM  32
#define ROWS_PER_BLOCK 64   // 2 teams x 32 rows

// Scratch (static device allocations are allowed; cudaMalloc is not)
__device__ float g_W[BATCH * NRODT];                    // rODT scores w (4 MB)
__device__ float g_Y[(size_t)BATCH * NFOREST * NCLASS]; // per-forest logits (4 MB)

// ---------------------------------------------------------------------------
// Kernel 1: fused ConditionGeneration -> permute -> GN -> 4x4 conv -> ReLU
//           -> GN -> 4-dot  => w[b, g].  One thread per (batch b, rODT g).
// ---------------------------------------------------------------------------
__global__ void cond_kernel(
    const float* __restrict__ x,    const float* __restrict__ w1,
    const float* __restrict__ b1,   const int*   __restrict__ perm,
    const float* __restrict__ gn1g, const float* __restrict__ gn1b,
    const float* __restrict__ w2a,  const float* __restrict__ b2a,
    const float* __restrict__ gn2g, const float* __restrict__ gn2b,
    const float* __restrict__ w2b,  const float* __restrict__ b2b)
{
    __shared__ float xs[NCOL];
    const int b = blockIdx.y;
    const int t = threadIdx.x;
    if (t < NCOL) xs[t] = x[b * NCOL + t];
    __syncthreads();

    const int g = blockIdx.x * 256 + t;

    const int4 p4 = ((const int4*)perm)[g];
    const int pv[4] = {p4.x, p4.y, p4.z, p4.w};
    float o[4];
#pragma unroll
    for (int i = 0; i < 4; i++) {
        const int p = pv[i];
        const int col = p & 63;             // permuted flat idx = cond*64 + col
        const int cond = p >> 6;
        const int wi = col * NCOND + cond;  // w1/b1 flat index (NCOL, NCOND)
        const float tv = fmaf(xs[col], w1[wi], b1[wi]);
        o[i] = 1.f / (1.f + __expf(-tv));
    }

    float mu = 0.f, s2 = 0.f;
#pragma unroll
    for (int i = 0; i < 4; i++) { mu += o[i]; s2 += o[i] * o[i]; }
    mu *= 0.25f;
    s2 = s2 * 0.25f - mu * mu;
    const float rstd = rsqrtf(s2 + EPSF);
    const float4 g1  = ((const float4*)gn1g)[g];
    const float4 be1 = ((const float4*)gn1b)[g];
    float hn[4];
    hn[0] = (o[0] - mu) * rstd * g1.x + be1.x;
    hn[1] = (o[1] - mu) * rstd * g1.y + be1.y;
    hn[2] = (o[2] - mu) * rstd * g1.z + be1.z;
    hn[3] = (o[3] - mu) * rstd * g1.w + be1.w;

    const float4 bb2 = ((const float4*)b2a)[g];
    float h2[4] = {bb2.x, bb2.y, bb2.z, bb2.w};
#pragma unroll
    for (int i = 0; i < 4; i++) {
        const float4 wr = ((const float4*)w2a)[g * 4 + i];
        h2[0] = fmaf(hn[i], wr.x, h2[0]);
        h2[1] = fmaf(hn[i], wr.y, h2[1]);
        h2[2] = fmaf(hn[i], wr.z, h2[2]);
        h2[3] = fmaf(hn[i], wr.w, h2[3]);
    }
#pragma unroll
    for (int i = 0; i < 4; i++) h2[i] = fmaxf(h2[i], 0.f);

    float mu2 = 0.f, t2 = 0.f;
#pragma unroll
    for (int i = 0; i < 4; i++) { mu2 += h2[i]; t2 += h2[i] * h2[i]; }
    mu2 *= 0.25f;
    t2 = t2 * 0.25f - mu2 * mu2;
    const float rstd2 = rsqrtf(t2 + EPSF);
    const float4 g2  = ((const float4*)gn2g)[g];
    const float4 be2 = ((const float4*)gn2b)[g];
    const float4 wb  = ((const float4*)w2b)[g];

    float wv = b2b[g];
    wv = fmaf((h2[0] - mu2) * rstd2 * g2.x + be2.x, wb.x, wv);
    wv = fmaf((h2[1] - mu2) * rstd2 * g2.y + be2.y, wb.y, wv);
    wv = fmaf((h2[2] - mu2) * rstd2 * g2.z + be2.z, wb.z, wv);
    wv = fmaf((h2[3] - mu2) * rstd2 * g2.w + be2.w, wb.w, wv);

    g_W[b * NRODT + g] = wv;
}

// ---------------------------------------------------------------------------
// Kernel 2: per (64-row tile, forest): softmax -> F = ws @ Es[f] -> LN ->
//           lin1 + ReLU -> LN -> lin2 ; per-forest logits to scratch.
// 256 threads = 2 teams of 128. Es[f] in dynamic smem (64 KB); lin1_w read
// from global (L1D-resident, identical across blocks). 2 blocks/SM.
// ---------------------------------------------------------------------------
__global__ void __launch_bounds__(256, 2) forest_kernel(
    const float* __restrict__ E,     const int*   __restrict__ swr,
    const float* __restrict__ ln1g,  const float* __restrict__ ln1b,
    const float* __restrict__ lin1w, const float* __restrict__ lin1b,
    const float* __restrict__ ln2g,  const float* __restrict__ ln2b,
    const float* __restrict__ lin2w, const float* __restrict__ lin2b)
{
    extern __shared__ __align__(16) float sm[];
    float* Es = sm;                 // [NEST][NHID]  64 KB
    __shared__ __align__(16) float L2w[NHID * NCLASS];
    __shared__ int idx[NEST];
    __shared__ __align__(16) float ws_s[2][NEST * TB];  // [team][e][r]
    __shared__ __align__(16) float zn_s[2][NHID * TB];  // [team][k][r]
    __shared__ float rsA[2][TB * 4], rsB[2][TB * 4];

    const int t    = threadIdx.x;       // 0..255
    const int team = t >> 7;            // 0,1
    const int tt   = t & 127;           // within team: channel / estimator id
    const int lane = t & 31;
    const int wid  = tt >> 5;           // warp within team 0..3
    const int f    = blockIdx.y;
    const int b0   = blockIdx.x * ROWS_PER_BLOCK + team * ROWS_PER_TEAM;

    if (t < NEST) idx[t] = swr[f * NEST + t];
    __syncthreads();

    // Gather Es[f] rows (coalesced float4, 8 warps)
    for (int e = (t >> 5); e < NEST; e += 8)
        ((float4*)(Es + e * NHID))[lane] =
            ((const float4*)(E + (size_t)idx[e] * NHID))[lane];
    for (int i = t; i < NHID * NCLASS; i += 256) L2w[i] = lin2w[i];

    const float l1g = ln1g[tt], l1bv = ln1b[tt];
    const float l2gv = ln2g[tt], l2bv = ln2b[tt];
    const float lb1 = lin1b[tt];
    const int myidx = idx[tt];
    float* const wsp = ws_s[team];
    float* const znp = zn_s[team];
    float* const rA  = rsA[team];
    float* const rB  = rsB[team];
    __syncthreads();

    for (int ch = 0; ch < ROWS_PER_TEAM / TB; ch++) {
        const int bb = b0 + ch * TB;

        // ---- softmax over estimators (thread tt = estimator), TB rows ----
        float v[TB], ev[TB];
#pragma unroll
        for (int r = 0; r < TB; r++)
            v[r] = g_W[(size_t)(bb + r) * NRODT + myidx];
#pragma unroll
        for (int r = 0; r < TB; r++) {
            float m = v[r];
            for (int o = 16; o > 0; o >>= 1)
                m = fmaxf(m, __shfl_xor_sync(0xffffffffu, m, o));
            if (lane == 0) rA[r * 4 + wid] = m;
        }
        __syncthreads();
#pragma unroll
        for (int r = 0; r < TB; r++) {
            const float m = fmaxf(fmaxf(rA[r * 4], rA[r * 4 + 1]),
                                  fmaxf(rA[r * 4 + 2], rA[r * 4 + 3]));
            ev[r] = __expf(v[r] - m);
            float s = ev[r];
            for (int o = 16; o > 0; o >>= 1)
                s += __shfl_xor_sync(0xffffffffu, s, o);
            if (lane == 0) rB[r * 4 + wid] = s;
        }
        __syncthreads();
#pragma unroll
        for (int r = 0; r < TB; r++) {
            const float s = rB[r * 4] + rB[r * 4 + 1] +
                            rB[r * 4 + 2] + rB[r * 4 + 3];
            wsp[tt * TB + r] = ev[r] * (1.f / s);
        }
        __syncthreads();

        // ---- F[r][tt] = sum_e ws[r][e] * Es[e][tt] ----
        float acc[TB];
#pragma unroll
        for (int r = 0; r < TB; r++) acc[r] = 0.f;
#pragma unroll 4
        for (int e = 0; e < NEST; e++) {
            const float es = Es[e * NHID + tt];
            const float4* wp = (const float4*)(wsp + e * TB);
            const float4 wa = wp[0], wb = wp[1], wc = wp[2], wd = wp[3];
            acc[0]  = fmaf(wa.x, es, acc[0]);
            acc[1]  = fmaf(wa.y, es, acc[1]);
            acc[2]  = fmaf(wa.z, es, acc[2]);
            acc[3]  = fmaf(wa.w, es, acc[3]);
            acc[4]  = fmaf(wb.x, es, acc[4]);
            acc[5]  = fmaf(wb.y, es, acc[5]);
            acc[6]  = fmaf(wb.z, es, acc[6]);
            acc[7]  = fmaf(wb.w, es, acc[7]);
            acc[8]  = fmaf(wc.x, es, acc[8]);
            acc[9]  = fmaf(wc.y, es, acc[9]);
            acc[10] = fmaf(wc.z, es, acc[10]);
            acc[11] = fmaf(wc.w, es, acc[11]);
            acc[12] = fmaf(wd.x, es, acc[12]);
            acc[13] = fmaf(wd.y, es, acc[13]);
            acc[14] = fmaf(wd.z, es, acc[14]);
            acc[15] = fmaf(wd.w, es, acc[15]);
        }

        // ---- LayerNorm 1 ----
#pragma unroll
        for (int r = 0; r < TB; r++) {
            float s = acc[r], s2 = acc[r] * acc[r];
            for (int o = 16; o > 0; o >>= 1) {
                s  += __shfl_xor_sync(0xffffffffu, s, o);
                s2 += __shfl_xor_sync(0xffffffffu, s2, o);
            }
            if (lane == 0) { rA[r * 4 + wid] = s; rB[r * 4 + wid] = s2; }
        }
        __syncthreads();
#pragma unroll
        for (int r = 0; r < TB; r++) {
            const float m = (rA[r * 4] + rA[r * 4 + 1] +
                             rA[r * 4 + 2] + rA[r * 4 + 3]) * (1.f / NHID);
            const float va = (rB[r * 4] + rB[r * 4 + 1] +
                              rB[r * 4 + 2] + rB[r * 4 + 3]) * (1.f / NHID) - m * m;
            const float rstd = rsqrtf(va + EPSF);
            znp[tt * TB + r] = (acc[r] - m) * rstd * l1g + l1bv;
        }
        __syncthreads();

        // ---- lin1 + ReLU (lin1w streamed from global/L1D) ----
#pragma unroll
        for (int r = 0; r < TB; r++) acc[r] = lb1;
#pragma unroll 4
        for (int k = 0; k < NHID; k++) {
            const float l = __ldg(&lin1w[k * NHID + tt]);
            const float4* zp = (const float4*)(znp + k * TB);
            const float4 za = zp[0], zb = zp[1], zc = zp[2], zd = zp[3];
            acc[0]  = fmaf(za.x, l, acc[0]);
            acc[1]  = fmaf(za.y, l, acc[1]);
            acc[2]  = fmaf(za.z, l, acc[2]);
            acc[3]  = fmaf(za.w, l, acc[3]);
            acc[4]  = fmaf(zb.x, l, acc[4]);
            acc[5]  = fmaf(zb.y, l, acc[5]);
            acc[6]  = fmaf(zb.z, l, acc[6]);
            acc[7]  = fmaf(zb.w, l, acc[7]);
            acc[8]  = fmaf(zc.x, l, acc[8]);
            acc[9]  = fmaf(zc.y, l, acc[9]);
            acc[10] = fmaf(zc.z, l, acc[10]);
            acc[11] = fmaf(zc.w, l, acc[11]);
            acc[12] = fmaf(zd.x, l, acc[12]);
            acc[13] = fmaf(zd.y, l, acc[13]);
            acc[14] = fmaf(zd.z, l, acc[14]);
            acc[15] = fmaf(zd.w, l, acc[15]);
        }
#pragma unroll
        for (int r = 0; r < TB; r++) acc[r] = fmaxf(acc[r], 0.f);

        // ---- LayerNorm 2 ----
#pragma unroll
        for (int r = 0; r < TB; r++) {
            float s = acc[r], s2 = acc[r] * acc[r];
            for (int o = 16; o > 0; o >>= 1) {
                s  += __shfl_xor_sync(0xffffffffu, s, o);
                s2 += __shfl_xor_sync(0xffffffffu, s2, o);
            }
            if (lane == 0) { rA[r * 4 + wid] = s; rB[r * 4 + wid] = s2; }
        }
        __syncthreads();   // also guards znp overwrite vs lin1 readers
#pragma unroll
        for (int r = 0; r < TB; r++) {
            const float m = (rA[r * 4] + rA[r * 4 + 1] +
                             rA[r * 4 + 2] + rA[r * 4 + 3]) * (1.f / NHID);
            const float va = (rB[r * 4] + rB[r * 4 + 1] +
                              rB[r * 4 + 2] + rB[r * 4 + 3]) * (1.f / NHID) - m * m;
            const float rstd = rsqrtf(va + EPSF);
            znp[tt * TB + r] = (acc[r] - m) * rstd * l2gv + l2bv;
        }
        __syncthreads();

        // ---- lin2 (128 -> 10): 160 (r,c) items over 128 team threads ----
        for (int it = tt; it < TB * NCLASS; it += 128) {
            const int r = it & (TB - 1);
            const int c = it >> 4;
            float y = lin2b[c];
#pragma unroll 4
            for (int k = 0; k < NHID; k++)
                y = fmaf(znp[k * TB + r], L2w[k * NCLASS + c], y);
            g_Y[((size_t)(bb + r) * NFOREST + f) * NCLASS + c] = y;
        }
        __syncthreads();   // before next chunk reuses wsp/rs
    }
}

// ---------------------------------------------------------------------------
// Kernel 3: deterministic mean over forests
// ---------------------------------------------------------------------------
__global__ void mean_kernel(float* __restrict__ out)
{
    const int i = blockIdx.x * 256 + threadIdx.x;
    if (i >= BATCH * NCLASS) return;
    const int b = i / NCLASS;
    const int c = i - b * NCLASS;
    const float* p = g_Y + (size_t)b * NFOREST * NCLASS + c;
    float s = 0.f;
#pragma unroll 4
    for (int f = 0; f < NFOREST; f++) s += p[f * NCLASS];
    out[i] = s * (1.f / NFOREST);
}

// ---------------------------------------------------------------------------
extern "C" void kernel_launch(void* const* d_in, const int* in_sizes, int n_in,
                              void* d_out, int out_size)
{
    const float* x     = (const float*)d_in[0];
    const float* w1    = (const float*)d_in[1];
    const float* b1    = (const float*)d_in[2];
    const int*   perm  = (const int*)  d_in[3];
    const float* gn1g  = (const float*)d_in[4];
    const float* gn1b  = (const float*)d_in[5];
    const float* w2a   = (const float*)d_in[6];
    const float* b2a   = (const float*)d_in[7];
    const float* gn2g  = (const float*)d_in[8];
    const float* gn2b  = (const float*)d_in[9];
    const float* w2b   = (const float*)d_in[10];
    const float* b2b   = (const float*)d_in[11];
    const float* E     = (const float*)d_in[12];
    const int*   swr   = (const int*)  d_in[13];
    const float* ln1g  = (const float*)d_in[14];
    const float* ln1b  = (const float*)d_in[15];
    const float* lin1w = (const float*)d_in[16];
    const float* lin1b = (const float*)d_in[17];
    const float* ln2g  = (const float*)d_in[18];
    const float* ln2b  = (const float*)d_in[19];
    const float* lin2w = (const float*)d_in[20];
    const float* lin2b = (const float*)d_in[21];

    const int dyn_smem = NEST * NHID * (int)sizeof(float);  // 64 KB (Es only)
    cudaFuncSetAttribute(forest_kernel,
                         cudaFuncAttributeMaxDynamicSharedMemorySize, dyn_smem);

    cond_kernel<<<dim3(NRODT / 256, BATCH), 256>>>(
        x, w1, b1, perm, gn1g, gn1b, w2a, b2a, gn2g, gn2b, w2b, b2b);

    forest_kernel<<<dim3(BATCH / ROWS_PER_BLOCK, NFOREST), 256, dyn_smem>>>(
        E, swr, ln1g, ln1b, lin1w, lin1b, ln2g, ln2b, lin2w, lin2b);

    mean_kernel<<<(BATCH * NCLASS + 255) / 256, 256>>>((float*)d_out);
}

// round 4
// speedup vs baseline: 2.6127x; 1.0775x over previous
#include <cuda_runtime.h>

#define BATCH   1024
#define NCOL    64
#define NCOND   64
#define NRODT   1024
#define NEST    128
#define NFOREST 100
#define NHID    128
#define NCLASS  10
#define EPSF    1e-5f
#define TB      16
#define ROWS_PER_TEAM  32
#define ROWS_PER_BLOCK 64   // 2 teams x 32 rows

// Scratch (static device arrays; cudaMalloc is forbidden)
__device__ float g_W [BATCH * NRODT];                    // rODT scores (4 MB)
__device__ float g_EW[BATCH * NRODT];                    // exp(w - rowmax) (4 MB)
__device__ float g_Y [(size_t)BATCH * NFOREST * NCLASS]; // per-forest logits

// ---- packed fp32x2 helpers (FFMA2 path, full fp32 precision) --------------
__device__ __forceinline__ void ffma2(unsigned long long& d,
                                      unsigned long long a,
                                      unsigned long long b) {
    asm("fma.rn.f32x2 %0, %1, %2, %0;" : "+l"(d) : "l"(a), "l"(b));
}
__device__ __forceinline__ unsigned long long dup2(float v) {
    unsigned long long r;
    asm("mov.b64 %0, {%1, %1};" : "=l"(r) : "f"(v));
    return r;
}
__device__ __forceinline__ void unpack2(float& lo, float& hi,
                                        unsigned long long v) {
    asm("mov.b64 {%0, %1}, %2;" : "=f"(lo), "=f"(hi) : "l"(v));
}

// ---------------------------------------------------------------------------
// Kernel 1: fused ConditionGeneration -> permute -> GN -> 4x4 conv -> ReLU
//           -> GN -> 4-dot  => w[b, g].  One thread per (batch b, rODT g).
// ---------------------------------------------------------------------------
__global__ void cond_kernel(
    const float* __restrict__ x,    const float* __restrict__ w1,
    const float* __restrict__ b1,   const int*   __restrict__ perm,
    const float* __restrict__ gn1g, const float* __restrict__ gn1b,
    const float* __restrict__ w2a,  const float* __restrict__ b2a,
    const float* __restrict__ gn2g, const float* __restrict__ gn2b,
    const float* __restrict__ w2b,  const float* __restrict__ b2b)
{
    __shared__ float xs[NCOL];
    const int b = blockIdx.y;
    const int t = threadIdx.x;
    if (t < NCOL) xs[t] = x[b * NCOL + t];
    __syncthreads();

    const int g = blockIdx.x * 256 + t;

    const int4 p4 = ((const int4*)perm)[g];
    const int pv[4] = {p4.x, p4.y, p4.z, p4.w};
    float o[4];
#pragma unroll
    for (int i = 0; i < 4; i++) {
        const int p = pv[i];
        const int col = p & 63;
        const int cond = p >> 6;
        const int wi = col * NCOND + cond;
        const float tv = fmaf(xs[col], w1[wi], b1[wi]);
        o[i] = 1.f / (1.f + __expf(-tv));
    }

    float mu = 0.f, s2 = 0.f;
#pragma unroll
    for (int i = 0; i < 4; i++) { mu += o[i]; s2 += o[i] * o[i]; }
    mu *= 0.25f;
    s2 = s2 * 0.25f - mu * mu;
    const float rstd = rsqrtf(s2 + EPSF);
    const float4 g1  = ((const float4*)gn1g)[g];
    const float4 be1 = ((const float4*)gn1b)[g];
    float hn[4];
    hn[0] = (o[0] - mu) * rstd * g1.x + be1.x;
    hn[1] = (o[1] - mu) * rstd * g1.y + be1.y;
    hn[2] = (o[2] - mu) * rstd * g1.z + be1.z;
    hn[3] = (o[3] - mu) * rstd * g1.w + be1.w;

    const float4 bb2 = ((const float4*)b2a)[g];
    float h2[4] = {bb2.x, bb2.y, bb2.z, bb2.w};
#pragma unroll
    for (int i = 0; i < 4; i++) {
        const float4 wr = ((const float4*)w2a)[g * 4 + i];
        h2[0] = fmaf(hn[i], wr.x, h2[0]);
        h2[1] = fmaf(hn[i], wr.y, h2[1]);
        h2[2] = fmaf(hn[i], wr.z, h2[2]);
        h2[3] = fmaf(hn[i], wr.w, h2[3]);
    }
#pragma unroll
    for (int i = 0; i < 4; i++) h2[i] = fmaxf(h2[i], 0.f);

    float mu2 = 0.f, t2 = 0.f;
#pragma unroll
    for (int i = 0; i < 4; i++) { mu2 += h2[i]; t2 += h2[i] * h2[i]; }
    mu2 *= 0.25f;
    t2 = t2 * 0.25f - mu2 * mu2;
    const float rstd2 = rsqrtf(t2 + EPSF);
    const float4 g2  = ((const float4*)gn2g)[g];
    const float4 be2 = ((const float4*)gn2b)[g];
    const float4 wb  = ((const float4*)w2b)[g];

    float wv = b2b[g];
    wv = fmaf((h2[0] - mu2) * rstd2 * g2.x + be2.x, wb.x, wv);
    wv = fmaf((h2[1] - mu2) * rstd2 * g2.y + be2.y, wb.y, wv);
    wv = fmaf((h2[2] - mu2) * rstd2 * g2.z + be2.z, wb.z, wv);
    wv = fmaf((h2[3] - mu2) * rstd2 * g2.w + be2.w, wb.w, wv);

    g_W[b * NRODT + g] = wv;
}

// ---------------------------------------------------------------------------
// Kernel 1.5: per-row global max + exp.  g_EW = exp(w - rowmax(w)).
// Subset softmax downstream is ratio-invariant to the shared max.
// ---------------------------------------------------------------------------
__global__ void expw_kernel()
{
    __shared__ float red[8];
    const int b = blockIdx.x;
    const int t = threadIdx.x;      // 256 threads, 4 values each
    const float4 v = ((const float4*)(g_W + b * NRODT))[t];
    float m = fmaxf(fmaxf(v.x, v.y), fmaxf(v.z, v.w));
#pragma unroll
    for (int o = 16; o > 0; o >>= 1)
        m = fmaxf(m, __shfl_xor_sync(0xffffffffu, m, o));
    if ((t & 31) == 0) red[t >> 5] = m;
    __syncthreads();
    m = red[0];
#pragma unroll
    for (int i = 1; i < 8; i++) m = fmaxf(m, red[i]);
    float4 e;
    e.x = __expf(v.x - m);
    e.y = __expf(v.y - m);
    e.z = __expf(v.z - m);
    e.w = __expf(v.w - m);
    ((float4*)(g_EW + b * NRODT))[t] = e;
}

// ---------------------------------------------------------------------------
// Kernel 2: per (64-row tile, forest): sum-normalize -> F = ws @ Es[f] -> LN
//           -> lin1 + ReLU -> LN -> lin2 ; logits to scratch.
// 256 threads = 2 teams of 128. GEMM inner loops use packed fma.rn.f32x2.
// ---------------------------------------------------------------------------
__global__ void __launch_bounds__(256, 2) forest_kernel(
    const float* __restrict__ E,     const int*   __restrict__ swr,
    const float* __restrict__ ln1g,  const float* __restrict__ ln1b,
    const float* __restrict__ lin1w, const float* __restrict__ lin1b,
    const float* __restrict__ ln2g,  const float* __restrict__ ln2b,
    const float* __restrict__ lin2w, const float* __restrict__ lin2b)
{
    extern __shared__ __align__(16) float sm[];
    float* Es = sm;                 // [NEST][NHID]  64 KB
    __shared__ __align__(16) float L2w[NHID * NCLASS];
    __shared__ int idx[NEST];
    __shared__ __align__(16) float ws_s[2][NEST * TB];  // [team][e][r]
    __shared__ __align__(16) float zn_s[2][NHID * TB];  // [team][k][r]
    __shared__ float rsA[2][TB * 4], rsB[2][TB * 4];

    const int t    = threadIdx.x;
    const int team = t >> 7;
    const int tt   = t & 127;
    const int lane = t & 31;
    const int wid  = tt >> 5;
    const int f    = blockIdx.y;
    const int b0   = blockIdx.x * ROWS_PER_BLOCK + team * ROWS_PER_TEAM;

    if (t < NEST) idx[t] = swr[f * NEST + t];
    __syncthreads();

    for (int e = (t >> 5); e < NEST; e += 8)
        ((float4*)(Es + e * NHID))[lane] =
            ((const float4*)(E + (size_t)idx[e] * NHID))[lane];
    for (int i = t; i < NHID * NCLASS; i += 256) L2w[i] = lin2w[i];

    const float l1g = ln1g[tt], l1bv = ln1b[tt];
    const float l2gv = ln2g[tt], l2bv = ln2b[tt];
    const float lb1 = lin1b[tt];
    const int myidx = idx[tt];
    float* const wsp = ws_s[team];
    float* const znp = zn_s[team];
    float* const rA  = rsA[team];
    float* const rB  = rsB[team];
    __syncthreads();

    for (int ch = 0; ch < ROWS_PER_TEAM / TB; ch++) {
        const int bb = b0 + ch * TB;

        // ---- normalized weights: v / sum(subset v), v = exp(w - rowmax) ----
        float v[TB];
#pragma unroll
        for (int r = 0; r < TB; r++)
            v[r] = g_EW[(size_t)(bb + r) * NRODT + myidx];
#pragma unroll
        for (int r = 0; r < TB; r++) {
            float s = v[r];
            for (int o = 16; o > 0; o >>= 1)
                s += __shfl_xor_sync(0xffffffffu, s, o);
            if (lane == 0) rB[r * 4 + wid] = s;
        }
        __syncthreads();
#pragma unroll
        for (int r = 0; r < TB; r++) {
            const float s = rB[r * 4] + rB[r * 4 + 1] +
                            rB[r * 4 + 2] + rB[r * 4 + 3];
            wsp[tt * TB + r] = v[r] * (1.f / s);
        }
        __syncthreads();

        // ---- F[r][tt] = sum_e ws[r][e] * Es[e][tt]  (packed f32x2) ----
        unsigned long long acc2[8];
#pragma unroll
        for (int j = 0; j < 8; j++) acc2[j] = 0ull;
#pragma unroll 4
        for (int e = 0; e < NEST; e++) {
            const unsigned long long esd = dup2(Es[e * NHID + tt]);
            const double2* wp = (const double2*)(wsp + e * TB);
            const double2 w0 = wp[0], w1 = wp[1], w2 = wp[2], w3 = wp[3];
            ffma2(acc2[0], __double_as_longlong(w0.x), esd);
            ffma2(acc2[1], __double_as_longlong(w0.y), esd);
            ffma2(acc2[2], __double_as_longlong(w1.x), esd);
            ffma2(acc2[3], __double_as_longlong(w1.y), esd);
            ffma2(acc2[4], __double_as_longlong(w2.x), esd);
            ffma2(acc2[5], __double_as_longlong(w2.y), esd);
            ffma2(acc2[6], __double_as_longlong(w3.x), esd);
            ffma2(acc2[7], __double_as_longlong(w3.y), esd);
        }
        float acc[TB];
#pragma unroll
        for (int j = 0; j < 8; j++) unpack2(acc[2 * j], acc[2 * j + 1], acc2[j]);

        // ---- LayerNorm 1 ----
#pragma unroll
        for (int r = 0; r < TB; r++) {
            float s = acc[r], s2 = acc[r] * acc[r];
            for (int o = 16; o > 0; o >>= 1) {
                s  += __shfl_xor_sync(0xffffffffu, s, o);
                s2 += __shfl_xor_sync(0xffffffffu, s2, o);
            }
            if (lane == 0) { rA[r * 4 + wid] = s; rB[r * 4 + wid] = s2; }
        }
        __syncthreads();
#pragma unroll
        for (int r = 0; r < TB; r++) {
            const float m = (rA[r * 4] + rA[r * 4 + 1] +
                             rA[r * 4 + 2] + rA[r * 4 + 3]) * (1.f / NHID);
            const float va = (rB[r * 4] + rB[r * 4 + 1] +
                              rB[r * 4 + 2] + rB[r * 4 + 3]) * (1.f / NHID) - m * m;
            const float rstd = rsqrtf(va + EPSF);
            znp[tt * TB + r] = (acc[r] - m) * rstd * l1g + l1bv;
        }
        __syncthreads();

        // ---- lin1 + ReLU  (lin1w via L1D, packed f32x2) ----
#pragma unroll
        for (int j = 0; j < 8; j++) acc2[j] = dup2(lb1);
#pragma unroll 4
        for (int k = 0; k < NHID; k++) {
            const unsigned long long ld = dup2(__ldg(&lin1w[k * NHID + tt]));
            const double2* zp = (const double2*)(znp + k * TB);
            const double2 z0 = zp[0], z1 = zp[1], z2 = zp[2], z3 = zp[3];
            ffma2(acc2[0], __double_as_longlong(z0.x), ld);
            ffma2(acc2[1], __double_as_longlong(z0.y), ld);
            ffma2(acc2[2], __double_as_longlong(z1.x), ld);
            ffma2(acc2[3], __double_as_longlong(z1.y), ld);
            ffma2(acc2[4], __double_as_longlong(z2.x), ld);
            ffma2(acc2[5], __double_as_longlong(z2.y), ld);
            ffma2(acc2[6], __double_as_longlong(z3.x), ld);
            ffma2(acc2[7], __double_as_longlong(z3.y), ld);
        }
#pragma unroll
        for (int j = 0; j < 8; j++) unpack2(acc[2 * j], acc[2 * j + 1], acc2[j]);
#pragma unroll
        for (int r = 0; r < TB; r++) acc[r] = fmaxf(acc[r], 0.f);

        // ---- LayerNorm 2 ----
#pragma unroll
        for (int r = 0; r < TB; r++) {
            float s = acc[r], s2 = acc[r] * acc[r];
            for (int o = 16; o > 0; o >>= 1) {
                s  += __shfl_xor_sync(0xffffffffu, s, o);
                s2 += __shfl_xor_sync(0xffffffffu, s2, o);
            }
            if (lane == 0) { rA[r * 4 + wid] = s; rB[r * 4 + wid] = s2; }
        }
        __syncthreads();
#pragma unroll
        for (int r = 0; r < TB; r++) {
            const float m = (rA[r * 4] + rA[r * 4 + 1] +
                             rA[r * 4 + 2] + rA[r * 4 + 3]) * (1.f / NHID);
            const float va = (rB[r * 4] + rB[r * 4 + 1] +
                              rB[r * 4 + 2] + rB[r * 4 + 3]) * (1.f / NHID) - m * m;
            const float rstd = rsqrtf(va + EPSF);
            znp[tt * TB + r] = (acc[r] - m) * rstd * l2gv + l2bv;
        }
        __syncthreads();

        // ---- lin2 (128 -> 10): 160 (r,c) items over 128 team threads ----
        for (int it = tt; it < TB * NCLASS; it += 128) {
            const int r = it & (TB - 1);
            const int c = it >> 4;
            float y = lin2b[c];
#pragma unroll 4
            for (int k = 0; k < NHID; k++)
                y = fmaf(znp[k * TB + r], L2w[k * NCLASS + c], y);
            g_Y[((size_t)(bb + r) * NFOREST + f) * NCLASS + c] = y;
        }
        __syncthreads();
    }
}

// ---------------------------------------------------------------------------
// Kernel 3: deterministic mean over forests
// ---------------------------------------------------------------------------
__global__ void mean_kernel(float* __restrict__ out)
{
    const int i = blockIdx.x * 256 + threadIdx.x;
    if (i >= BATCH * NCLASS) return;
    const int b = i / NCLASS;
    const int c = i - b * NCLASS;
    const float* p = g_Y + (size_t)b * NFOREST * NCLASS + c;
    float s = 0.f;
#pragma unroll 4
    for (int f = 0; f < NFOREST; f++) s += p[f * NCLASS];
    out[i] = s * (1.f / NFOREST);
}

// ---------------------------------------------------------------------------
extern "C" void kernel_launch(void* const* d_in, const int* in_sizes, int n_in,
                              void* d_out, int out_size)
{
    const float* x     = (const float*)d_in[0];
    const float* w1    = (const float*)d_in[1];
    const float* b1    = (const float*)d_in[2];
    const int*   perm  = (const int*)  d_in[3];
    const float* gn1g  = (const float*)d_in[4];
    const float* gn1b  = (const float*)d_in[5];
    const float* w2a   = (const float*)d_in[6];
    const float* b2a   = (const float*)d_in[7];
    const float* gn2g  = (const float*)d_in[8];
    const float* gn2b  = (const float*)d_in[9];
    const float* w2b   = (const float*)d_in[10];
    const float* b2b   = (const float*)d_in[11];
    const float* E     = (const float*)d_in[12];
    const int*   swr   = (const int*)  d_in[13];
    const float* ln1g  = (const float*)d_in[14];
    const float* ln1b  = (const float*)d_in[15];
    const float* lin1w = (const float*)d_in[16];
    const float* lin1b = (const float*)d_in[17];
    const float* ln2g  = (const float*)d_in[18];
    const float* ln2b  = (const float*)d_in[19];
    const float* lin2w = (const float*)d_in[20];
    const float* lin2b = (const float*)d_in[21];

    const int dyn_smem = NEST * NHID * (int)sizeof(float);  // 64 KB (Es only)
    cudaFuncSetAttribute(forest_kernel,
                         cudaFuncAttributeMaxDynamicSharedMemorySize, dyn_smem);

    cond_kernel<<<dim3(NRODT / 256, BATCH), 256>>>(
        x, w1, b1, perm, gn1g, gn1b, w2a, b2a, gn2g, gn2b, w2b, b2b);

    expw_kernel<<<BATCH, 256>>>();

    forest_kernel<<<dim3(BATCH / ROWS_PER_BLOCK, NFOREST), 256, dyn_smem>>>(
        E, swr, ln1g, ln1b, lin1w, lin1b, ln2g, ln2b, lin2w, lin2b);

    mean_kernel<<<(BATCH * NCLASS + 255) / 256, 256>>>((float*)d_out);
}

// round 6
// speedup vs baseline: 6.5895x; 2.5221x over previous
#include <cuda_runtime.h>
#include <cuda_bf16.h>
#include <cstdint>

#define BATCH   1024
#define NCOL    64
#define NCOND   64
#define NRODT   1024
#define NEST    128
#define NFOREST 100
#define NHID    128
#define NCLASS  10
#define EPSF    1e-5f

// smem word layout (uint32 units), 68-word (272B) padded rows
#define SW    68
#define W_AHI 0
#define W_ALO 8704          // 128*68
#define W_B1H 17408
#define W_B1L 26112
#define W_B2H 34816
#define W_B2L 43520
#define W_B3H 52224
#define W_B3L 53312         // 52224 + 16*68
#define SMEM_WORDS 54400    // 217,600 bytes

// ---------------- scratch ---------------------------------------------------
__device__ float g_W  [BATCH * NRODT];
__device__ float g_EW [BATCH * NRODT];            // exp(w-rowmax), [b][g]
__device__ float g_EWT[NRODT * BATCH];            // transposed, [g][b]
__device__ float g_Y  [(size_t)NFOREST * BATCH * NCLASS];
__device__ uint32_t g_EsHi[NFOREST * 8192];       // B1 [n][k-words] per forest
__device__ uint32_t g_EsLo[NFOREST * 8192];
__device__ uint32_t g_L1Hi[8192];                 // B2
__device__ uint32_t g_L1Lo[8192];
__device__ uint32_t g_L2Hi[1024];                 // B3 (16 rows x 64 words)
__device__ uint32_t g_L2Lo[1024];

// ---------------- helpers ----------------------------------------------------
__device__ __forceinline__ uint32_t pack_bf16(float a, float b) {
    __nv_bfloat16 ha = __float2bfloat16(a), hb = __float2bfloat16(b);
    return (uint32_t)__bfloat16_as_ushort(ha)
         | ((uint32_t)__bfloat16_as_ushort(hb) << 16);
}
__device__ __forceinline__ void split2(float a, float b,
                                       uint32_t& hi, uint32_t& lo) {
    __nv_bfloat16 ha = __float2bfloat16(a), hb = __float2bfloat16(b);
    float ra = a - __bfloat162float(ha);
    float rb = b - __bfloat162float(hb);
    hi = (uint32_t)__bfloat16_as_ushort(ha)
       | ((uint32_t)__bfloat16_as_ushort(hb) << 16);
    lo = pack_bf16(ra, rb);
}
__device__ __forceinline__ void mma_bf16(float* c,
    uint32_t a0, uint32_t a1, uint32_t a2, uint32_t a3,
    uint32_t b0, uint32_t b1) {
    asm volatile(
        "mma.sync.aligned.m16n8k16.row.col.f32.bf16.bf16.f32 "
        "{%0,%1,%2,%3},{%4,%5,%6,%7},{%8,%9},{%0,%1,%2,%3};"
        : "+f"(c[0]), "+f"(c[1]), "+f"(c[2]), "+f"(c[3])
        : "r"(a0), "r"(a1), "r"(a2), "r"(a3), "r"(b0), "r"(b1));
}
__device__ __forceinline__ float fast_sigmoid(float x) {
    float th;
    asm("tanh.approx.f32 %0, %1;" : "=f"(th) : "f"(x * 0.5f));
    return fmaf(0.5f, th, 0.5f);
}

// ---------------------------------------------------------------------------
// Kernel 1: condition generation -> rODT scores w[b,g]
// ---------------------------------------------------------------------------
__global__ void cond_kernel(
    const float* __restrict__ x,    const float* __restrict__ w1,
    const float* __restrict__ b1,   const int*   __restrict__ perm,
    const float* __restrict__ gn1g, const float* __restrict__ gn1b,
    const float* __restrict__ w2a,  const float* __restrict__ b2a,
    const float* __restrict__ gn2g, const float* __restrict__ gn2b,
    const float* __restrict__ w2b,  const float* __restrict__ b2b)
{
    __shared__ float xs[NCOL];
    const int b = blockIdx.y;
    const int t = threadIdx.x;
    if (t < NCOL) xs[t] = x[b * NCOL + t];
    __syncthreads();

    const int g = blockIdx.x * 256 + t;
    const int4 p4 = ((const int4*)perm)[g];
    const int pv[4] = {p4.x, p4.y, p4.z, p4.w};
    float o[4];
#pragma unroll
    for (int i = 0; i < 4; i++) {
        const int p = pv[i];
        const int wi = (p & 63) * NCOND + (p >> 6);
        o[i] = fast_sigmoid(fmaf(xs[p & 63], w1[wi], b1[wi]));
    }
    float mu = 0.f, s2 = 0.f;
#pragma unroll
    for (int i = 0; i < 4; i++) { mu += o[i]; s2 += o[i] * o[i]; }
    mu *= 0.25f; s2 = s2 * 0.25f - mu * mu;
    const float rstd = rsqrtf(s2 + EPSF);
    const float4 g1  = ((const float4*)gn1g)[g];
    const float4 be1 = ((const float4*)gn1b)[g];
    float hn[4];
    hn[0] = (o[0] - mu) * rstd * g1.x + be1.x;
    hn[1] = (o[1] - mu) * rstd * g1.y + be1.y;
    hn[2] = (o[2] - mu) * rstd * g1.z + be1.z;
    hn[3] = (o[3] - mu) * rstd * g1.w + be1.w;

    const float4 bb2 = ((const float4*)b2a)[g];
    float h2[4] = {bb2.x, bb2.y, bb2.z, bb2.w};
#pragma unroll
    for (int i = 0; i < 4; i++) {
        const float4 wr = ((const float4*)w2a)[g * 4 + i];
        h2[0] = fmaf(hn[i], wr.x, h2[0]);
        h2[1] = fmaf(hn[i], wr.y, h2[1]);
        h2[2] = fmaf(hn[i], wr.z, h2[2]);
        h2[3] = fmaf(hn[i], wr.w, h2[3]);
    }
#pragma unroll
    for (int i = 0; i < 4; i++) h2[i] = fmaxf(h2[i], 0.f);
    float mu2 = 0.f, t2 = 0.f;
#pragma unroll
    for (int i = 0; i < 4; i++) { mu2 += h2[i]; t2 += h2[i] * h2[i]; }
    mu2 *= 0.25f; t2 = t2 * 0.25f - mu2 * mu2;
    const float rstd2 = rsqrtf(t2 + EPSF);
    const float4 g2  = ((const float4*)gn2g)[g];
    const float4 be2 = ((const float4*)gn2b)[g];
    const float4 wb  = ((const float4*)w2b)[g];
    float wv = b2b[g];
    wv = fmaf((h2[0] - mu2) * rstd2 * g2.x + be2.x, wb.x, wv);
    wv = fmaf((h2[1] - mu2) * rstd2 * g2.y + be2.y, wb.y, wv);
    wv = fmaf((h2[2] - mu2) * rstd2 * g2.z + be2.z, wb.z, wv);
    wv = fmaf((h2[3] - mu2) * rstd2 * g2.w + be2.w, wb.w, wv);
    g_W[b * NRODT + g] = wv;
}

// ---------------------------------------------------------------------------
// Kernel 1.5: g_EW[b][g] = exp(w - rowmax)
// ---------------------------------------------------------------------------
__global__ void expw_kernel()
{
    __shared__ float red[8];
    const int b = blockIdx.x;
    const int t = threadIdx.x;
    const float4 v = ((const float4*)(g_W + b * NRODT))[t];
    float m = fmaxf(fmaxf(v.x, v.y), fmaxf(v.z, v.w));
#pragma unroll
    for (int o = 16; o > 0; o >>= 1)
        m = fmaxf(m, __shfl_xor_sync(0xffffffffu, m, o));
    if ((t & 31) == 0) red[t >> 5] = m;
    __syncthreads();
    m = red[0];
#pragma unroll
    for (int i = 1; i < 8; i++) m = fmaxf(m, red[i]);
    float4 e;
    e.x = __expf(v.x - m); e.y = __expf(v.y - m);
    e.z = __expf(v.z - m); e.w = __expf(v.w - m);
    ((float4*)(g_EW + b * NRODT))[t] = e;
}

// tiled transpose: g_EWT[g][b] = g_EW[b][g]
__global__ void transpose_ew()
{
    __shared__ float tile[32][33];
    const int bx = blockIdx.x * 32, by = blockIdx.y * 32;
    const int tx = threadIdx.x, ty = threadIdx.y;   // 32 x 8
#pragma unroll
    for (int j = 0; j < 32; j += 8)
        tile[ty + j][tx] = g_EW[(by + ty + j) * NRODT + bx + tx];
    __syncthreads();
#pragma unroll
    for (int j = 0; j < 32; j += 8)
        g_EWT[(bx + ty + j) * BATCH + by + tx] = tile[tx][ty + j];
}

// ---------------------------------------------------------------------------
// Prep: split B operands into hi/lo bf16 word tiles ([n][64 words])
// ---------------------------------------------------------------------------
__global__ void prep_es(const float* __restrict__ E, const int* __restrict__ swr)
{
    __shared__ int idx[NEST];
    const int f = blockIdx.x;
    const int t = threadIdx.x;            // row n = hidden channel
    idx[t] = swr[f * NEST + t];
    __syncthreads();
    uint32_t* hiP = g_EsHi + f * 8192 + t * 64;
    uint32_t* loP = g_EsLo + f * 8192 + t * 64;
    for (int w = 0; w < 64; w++) {
        const float v0 = E[(size_t)idx[2 * w]     * NHID + t];
        const float v1 = E[(size_t)idx[2 * w + 1] * NHID + t];
        uint32_t hi, lo;
        split2(v0, v1, hi, lo);
        hiP[w] = hi; loP[w] = lo;
    }
}
__global__ void prep_l1(const float* __restrict__ lin1w)
{
    const int t = threadIdx.x;            // row n = h2
    for (int w = 0; w < 64; w++) {
        const float v0 = lin1w[(2 * w) * NHID + t];
        const float v1 = lin1w[(2 * w + 1) * NHID + t];
        uint32_t hi, lo;
        split2(v0, v1, hi, lo);
        g_L1Hi[t * 64 + w] = hi; g_L1Lo[t * 64 + w] = lo;
    }
}
__global__ void prep_l2(const float* __restrict__ lin2w)
{
    const int t = threadIdx.x;            // word index = k-pair
    for (int n = 0; n < 16; n++) {
        const float v0 = (n < NCLASS) ? lin2w[(2 * t) * NCLASS + n] : 0.f;
        const float v1 = (n < NCLASS) ? lin2w[(2 * t + 1) * NCLASS + n] : 0.f;
        uint32_t hi, lo;
        split2(v0, v1, hi, lo);
        g_L2Hi[n * 64 + t] = hi; g_L2Lo[n * 64 + t] = lo;
    }
}

// ---------------------------------------------------------------------------
// Kernel 2: HMMA forest kernel.  Block = (128-row tile, forest f), 8 warps.
// Warp w owns rows w*16..w*16+15 over the full N range -> no cross-warp
// dependencies after the initial load barrier.
// ---------------------------------------------------------------------------
__global__ void __launch_bounds__(256, 1) forest_mma(
    const int*   __restrict__ swr,
    const float* __restrict__ ln1g, const float* __restrict__ ln1b,
    const float* __restrict__ lin1b,
    const float* __restrict__ ln2g, const float* __restrict__ ln2b,
    const float* __restrict__ lin2b)
{
    extern __shared__ __align__(16) uint32_t sw4[];
    __shared__ float Spart[2][128];
    __shared__ float pg1[128], pb1[128], plb[128], pg2[128], pb2[128];
    __shared__ float pl2b[16];
    __shared__ int idxs[NEST];

    const int t = threadIdx.x;
    const int f = blockIdx.y;
    const int b0 = blockIdx.x * 128;
    const int w = t >> 5, lane = t & 31, g = lane >> 2, tg = lane & 3;
    const int mbase = w * 16;

    if (t < 128) {
        idxs[t] = swr[f * NEST + t];
        pg1[t] = ln1g[t]; pb1[t] = ln1b[t];
        plb[t] = lin1b[t];
        pg2[t] = ln2g[t]; pb2[t] = ln2b[t];
    }
    if (t < 16) pl2b[t] = (t < NCLASS) ? lin2b[t] : 0.f;
    __syncthreads();

    // ---- copy pre-split B tiles into padded smem (uint4) ----
    {
        uint4* d = (uint4*)sw4;
        const uint4* s1h = (const uint4*)(g_EsHi + f * 8192);
        const uint4* s1l = (const uint4*)(g_EsLo + f * 8192);
        const uint4* s2h = (const uint4*)g_L1Hi;
        const uint4* s2l = (const uint4*)g_L1Lo;
        for (int i = t; i < 2048; i += 256) {
            const int n = i >> 4, q = i & 15;
            const int dd = n * 17 + q;
            d[(W_B1H >> 2) + dd] = s1h[i];
            d[(W_B1L >> 2) + dd] = s1l[i];
            d[(W_B2H >> 2) + dd] = s2h[i];
            d[(W_B2L >> 2) + dd] = s2l[i];
        }
        const uint4* s3h = (const uint4*)g_L2Hi;
        const uint4* s3l = (const uint4*)g_L2Lo;
        if (t < 256) {
            for (int i = t; i < 256; i += 256) {
                const int n = i >> 4, q = i & 15;
                const int dd = n * 17 + q;
                d[(W_B3H >> 2) + dd] = s3h[i];
                d[(W_B3L >> 2) + dd] = s3l[i];
            }
        }
    }

    // ---- build A1 = gathered EW subset (split bf16), and row sums ----
    {
        const int m = t & 127, half = t >> 7;
        float s = 0.f;
        const float* ew = g_EWT + b0 + m;
        uint32_t* AH = sw4 + W_AHI + m * SW + half * 32;
        uint32_t* AL = sw4 + W_ALO + m * SW + half * 32;
#pragma unroll 4
        for (int j = 0; j < 32; j++) {
            const int e = half * 64 + 2 * j;
            const float a0 = ew[(size_t)idxs[e]     * BATCH];
            const float a1 = ew[(size_t)idxs[e + 1] * BATCH];
            s += a0 + a1;
            uint32_t hi, lo;
            split2(a0, a1, hi, lo);
            AH[j] = hi; AL[j] = lo;
        }
        Spart[half][m] = s;
    }
    __syncthreads();

    const int rowA = (mbase + g) * SW;
    const int rowB = (mbase + g + 8) * SW;

    // =============== GEMM1: D = A1 @ B1 (Es) ===============
    float C[16][4];
#pragma unroll
    for (int nt = 0; nt < 16; nt++)
#pragma unroll
        for (int j = 0; j < 4; j++) C[nt][j] = 0.f;

    for (int ks = 0; ks < 8; ks++) {
        const int kw = ks * 8 + tg;
        const uint32_t ah0 = sw4[W_AHI + rowA + kw];
        const uint32_t ah1 = sw4[W_AHI + rowB + kw];
        const uint32_t ah2 = sw4[W_AHI + rowA + kw + 4];
        const uint32_t ah3 = sw4[W_AHI + rowB + kw + 4];
        const uint32_t al0 = sw4[W_ALO + rowA + kw];
        const uint32_t al1 = sw4[W_ALO + rowB + kw];
        const uint32_t al2 = sw4[W_ALO + rowA + kw + 4];
        const uint32_t al3 = sw4[W_ALO + rowB + kw + 4];
#pragma unroll
        for (int nt = 0; nt < 16; nt++) {
            const int bn = W_B1H + (nt * 8 + g) * SW + kw;
            const uint32_t bh0 = sw4[bn], bh1 = sw4[bn + 4];
            const uint32_t bl0 = sw4[bn + 8704], bl1 = sw4[bn + 8704 + 4];
            mma_bf16(C[nt], ah0, ah1, ah2, ah3, bh0, bh1);
            mma_bf16(C[nt], ah0, ah1, ah2, ah3, bl0, bl1);
            mma_bf16(C[nt], al0, al1, al2, al3, bh0, bh1);
        }
    }

    // ---- epilogue 1: normalize by S, LN1, split -> A tile ----
    {
        const float SA = Spart[0][mbase + g] + Spart[1][mbase + g];
        const float SB = Spart[0][mbase + g + 8] + Spart[1][mbase + g + 8];
        const float iA = 1.f / SA, iB = 1.f / SB;
        float sA = 0.f, qA = 0.f, sB = 0.f, qB = 0.f;
#pragma unroll
        for (int nt = 0; nt < 16; nt++) {
            C[nt][0] *= iA; C[nt][1] *= iA;
            C[nt][2] *= iB; C[nt][3] *= iB;
            sA += C[nt][0] + C[nt][1];
            qA += C[nt][0] * C[nt][0] + C[nt][1] * C[nt][1];
            sB += C[nt][2] + C[nt][3];
            qB += C[nt][2] * C[nt][2] + C[nt][3] * C[nt][3];
        }
#pragma unroll
        for (int o = 1; o <= 2; o <<= 1) {
            sA += __shfl_xor_sync(0xffffffffu, sA, o);
            qA += __shfl_xor_sync(0xffffffffu, qA, o);
            sB += __shfl_xor_sync(0xffffffffu, sB, o);
            qB += __shfl_xor_sync(0xffffffffu, qB, o);
        }
        const float mA = sA * (1.f / NHID);
        const float rA = rsqrtf(qA * (1.f / NHID) - mA * mA + EPSF);
        const float mB = sB * (1.f / NHID);
        const float rB = rsqrtf(qB * (1.f / NHID) - mB * mB + EPSF);
#pragma unroll
        for (int nt = 0; nt < 16; nt++) {
            const int n0 = nt * 8 + tg * 2, n1 = n0 + 1;
            const float zA0 = (C[nt][0] - mA) * rA * pg1[n0] + pb1[n0];
            const float zA1 = (C[nt][1] - mA) * rA * pg1[n1] + pb1[n1];
            const float zB0 = (C[nt][2] - mB) * rB * pg1[n0] + pb1[n0];
            const float zB1 = (C[nt][3] - mB) * rB * pg1[n1] + pb1[n1];
            uint32_t hi, lo;
            const int wa = nt * 4 + tg;
            split2(zA0, zA1, hi, lo);
            sw4[W_AHI + rowA + wa] = hi; sw4[W_ALO + rowA + wa] = lo;
            split2(zB0, zB1, hi, lo);
            sw4[W_AHI + rowB + wa] = hi; sw4[W_ALO + rowB + wa] = lo;
        }
        __syncwarp();
    }

    // =============== GEMM2: D = z1 @ lin1w ===============
#pragma unroll
    for (int nt = 0; nt < 16; nt++)
#pragma unroll
        for (int j = 0; j < 4; j++) C[nt][j] = 0.f;

    for (int ks = 0; ks < 8; ks++) {
        const int kw = ks * 8 + tg;
        const uint32_t ah0 = sw4[W_AHI + rowA + kw];
        const uint32_t ah1 = sw4[W_AHI + rowB + kw];
        const uint32_t ah2 = sw4[W_AHI + rowA + kw + 4];
        const uint32_t ah3 = sw4[W_AHI + rowB + kw + 4];
        const uint32_t al0 = sw4[W_ALO + rowA + kw];
        const uint32_t al1 = sw4[W_ALO + rowB + kw];
        const uint32_t al2 = sw4[W_ALO + rowA + kw + 4];
        const uint32_t al3 = sw4[W_ALO + rowB + kw + 4];
#pragma unroll
        for (int nt = 0; nt < 16; nt++) {
            const int bn = W_B2H + (nt * 8 + g) * SW + kw;
            const uint32_t bh0 = sw4[bn], bh1 = sw4[bn + 4];
            const uint32_t bl0 = sw4[bn + 8704], bl1 = sw4[bn + 8704 + 4];
            mma_bf16(C[nt], ah0, ah1, ah2, ah3, bh0, bh1);
            mma_bf16(C[nt], ah0, ah1, ah2, ah3, bl0, bl1);
            mma_bf16(C[nt], al0, al1, al2, al3, bh0, bh1);
        }
    }

    // ---- epilogue 2: +bias, ReLU, LN2, split -> A tile ----
    {
        float sA = 0.f, qA = 0.f, sB = 0.f, qB = 0.f;
#pragma unroll
        for (int nt = 0; nt < 16; nt++) {
            const int n0 = nt * 8 + tg * 2, n1 = n0 + 1;
            C[nt][0] = fmaxf(C[nt][0] + plb[n0], 0.f);
            C[nt][1] = fmaxf(C[nt][1] + plb[n1], 0.f);
            C[nt][2] = fmaxf(C[nt][2] + plb[n0], 0.f);
            C[nt][3] = fmaxf(C[nt][3] + plb[n1], 0.f);
            sA += C[nt][0] + C[nt][1];
            qA += C[nt][0] * C[nt][0] + C[nt][1] * C[nt][1];
            sB += C[nt][2] + C[nt][3];
            qB += C[nt][2] * C[nt][2] + C[nt][3] * C[nt][3];
        }
#pragma unroll
        for (int o = 1; o <= 2; o <<= 1) {
            sA += __shfl_xor_sync(0xffffffffu, sA, o);
            qA += __shfl_xor_sync(0xffffffffu, qA, o);
            sB += __shfl_xor_sync(0xffffffffu, sB, o);
            qB += __shfl_xor_sync(0xffffffffu, qB, o);
        }
        const float mA = sA * (1.f / NHID);
        const float rA = rsqrtf(qA * (1.f / NHID) - mA * mA + EPSF);
        const float mB = sB * (1.f / NHID);
        const float rB = rsqrtf(qB * (1.f / NHID) - mB * mB + EPSF);
#pragma unroll
        for (int nt = 0; nt < 16; nt++) {
            const int n0 = nt * 8 + tg * 2, n1 = n0 + 1;
            const float zA0 = (C[nt][0] - mA) * rA * pg2[n0] + pb2[n0];
            const float zA1 = (C[nt][1] - mA) * rA * pg2[n1] + pb2[n1];
            const float zB0 = (C[nt][2] - mB) * rB * pg2[n0] + pb2[n0];
            const float zB1 = (C[nt][3] - mB) * rB * pg2[n1] + pb2[n1];
            uint32_t hi, lo;
            const int wa = nt * 4 + tg;
            split2(zA0, zA1, hi, lo);
            sw4[W_AHI + rowA + wa] = hi; sw4[W_ALO + rowA + wa] = lo;
            split2(zB0, zB1, hi, lo);
            sw4[W_AHI + rowB + wa] = hi; sw4[W_ALO + rowB + wa] = lo;
        }
        __syncwarp();
    }

    // =============== GEMM3: logits = z2 @ lin2w (N=16 padded) ===============
    float Y[2][4];
#pragma unroll
    for (int nt = 0; nt < 2; nt++)
#pragma unroll
        for (int j = 0; j < 4; j++) Y[nt][j] = 0.f;

#pragma unroll
    for (int ks = 0; ks < 8; ks++) {
        const int kw = ks * 8 + tg;
        const uint32_t ah0 = sw4[W_AHI + rowA + kw];
        const uint32_t ah1 = sw4[W_AHI + rowB + kw];
        const uint32_t ah2 = sw4[W_AHI + rowA + kw + 4];
        const uint32_t ah3 = sw4[W_AHI + rowB + kw + 4];
        const uint32_t al0 = sw4[W_ALO + rowA + kw];
        const uint32_t al1 = sw4[W_ALO + rowB + kw];
        const uint32_t al2 = sw4[W_ALO + rowA + kw + 4];
        const uint32_t al3 = sw4[W_ALO + rowB + kw + 4];
#pragma unroll
        for (int nt = 0; nt < 2; nt++) {
            const int bn = W_B3H + (nt * 8 + g) * SW + kw;
            const uint32_t bh0 = sw4[bn], bh1 = sw4[bn + 4];
            const uint32_t bl0 = sw4[bn + 1088], bl1 = sw4[bn + 1088 + 4];
            mma_bf16(Y[nt], ah0, ah1, ah2, ah3, bh0, bh1);
            mma_bf16(Y[nt], ah0, ah1, ah2, ah3, bl0, bl1);
            mma_bf16(Y[nt], al0, al1, al2, al3, bh0, bh1);
        }
    }

    // ---- write logits ----
    {
        float* yA = g_Y + ((size_t)f * BATCH + b0 + mbase + g) * NCLASS;
        float* yB = g_Y + ((size_t)f * BATCH + b0 + mbase + g + 8) * NCLASS;
#pragma unroll
        for (int nt = 0; nt < 2; nt++) {
            const int n0 = nt * 8 + tg * 2, n1 = n0 + 1;
            if (n0 < NCLASS) {
                yA[n0] = Y[nt][0] + pl2b[n0];
                yB[n0] = Y[nt][2] + pl2b[n0];
            }
            if (n1 < NCLASS) {
                yA[n1] = Y[nt][1] + pl2b[n1];
                yB[n1] = Y[nt][3] + pl2b[n1];
            }
        }
    }
}

// ---------------------------------------------------------------------------
// Kernel 3: mean over forests, 4-way f-split per block
// ---------------------------------------------------------------------------
__global__ void mean_kernel(float* __restrict__ out)
{
    __shared__ float part[4][64];
    const int t = threadIdx.x;
    const int i = blockIdx.x * 64 + (t & 63);
    const int fg = t >> 6;
    float s = 0.f;
#pragma unroll 5
    for (int f = fg * 25; f < fg * 25 + 25; f++)
        s += g_Y[(size_t)f * (BATCH * NCLASS) + i];
    part[fg][t & 63] = s;
    __syncthreads();
    if (t < 64)
        out[blockIdx.x * 64 + t] =
            (part[0][t] + part[1][t] + part[2][t] + part[3][t]) * (1.f / NFOREST);
}

// ---------------------------------------------------------------------------
extern "C" void kernel_launch(void* const* d_in, const int* in_sizes, int n_in,
                              void* d_out, int out_size)
{
    const float* x     = (const float*)d_in[0];
    const float* w1    = (const float*)d_in[1];
    const float* b1    = (const float*)d_in[2];
    const int*   perm  = (const int*)  d_in[3];
    const float* gn1g  = (const float*)d_in[4];
    const float* gn1b  = (const float*)d_in[5];
    const float* w2a   = (const float*)d_in[6];
    const float* b2a   = (const float*)d_in[7];
    const float* gn2g  = (const float*)d_in[8];
    const float* gn2b  = (const float*)d_in[9];
    const float* w2b   = (const float*)d_in[10];
    const float* b2b   = (const float*)d_in[11];
    const float* E     = (const float*)d_in[12];
    const int*   swr   = (const int*)  d_in[13];
    const float* ln1g  = (const float*)d_in[14];
    const float* ln1b  = (const float*)d_in[15];
    const float* lin1w = (const float*)d_in[16];
    const float* lin1b = (const float*)d_in[17];
    const float* ln2g  = (const float*)d_in[18];
    const float* ln2b  = (const float*)d_in[19];
    const float* lin2w = (const float*)d_in[20];
    const float* lin2b = (const float*)d_in[21];

    const int dyn_smem = SMEM_WORDS * 4;   // 217,600 B
    cudaFuncSetAttribute(forest_mma,
                         cudaFuncAttributeMaxDynamicSharedMemorySize, dyn_smem);

    cond_kernel<<<dim3(NRODT / 256, BATCH), 256>>>(
        x, w1, b1, perm, gn1g, gn1b, w2a, b2a, gn2g, gn2b, w2b, b2b);
    expw_kernel<<<BATCH, 256>>>();
    transpose_ew<<<dim3(NRODT / 32, BATCH / 32), dim3(32, 8)>>>();
    prep_es<<<NFOREST, 128>>>(E, swr);
    prep_l1<<<1, 128>>>(lin1w);
    prep_l2<<<1, 64>>>(lin2w);

    forest_mma<<<dim3(BATCH / 128, NFOREST), 256, dyn_smem>>>(
        swr, ln1g, ln1b, lin1b, ln2g, ln2b, lin2b);

    mean_kernel<<<BATCH * NCLASS / 64, 256>>>((float*)d_out);
}

// round 7
// speedup vs baseline: 7.8717x; 1.1946x over previous
#include <cuda_runtime.h>
#include <cuda_bf16.h>
#include <cstdint>

#define BATCH   1024
#define NCOL    64
#define NCOND   64
#define NRODT   1024
#define NEST    128
#define NFOREST 100
#define NHID    128
#define NCLASS  10
#define EPSF    1e-5f

// smem word layout (uint32 units), 68-word (272B) padded rows
#define SW    68
#define W_AHI 0
#define W_ALO 8704          // 128*68
#define W_B1H 17408
#define W_B1L 26112
#define W_B2H 34816
#define W_B2L 43520
#define W_B3H 52224
#define W_B3L 53312         // 52224 + 16*68
#define SMEM_WORDS 54400    // 217,600 bytes

// ---------------- scratch ---------------------------------------------------
__device__ float g_W  [BATCH * NRODT];
__device__ float g_rmax[BATCH];
__device__ float g_EWT[NRODT * BATCH];            // exp(w-rowmax), [g][b]
__device__ float g_Y  [(size_t)NFOREST * BATCH * NCLASS];
__device__ uint32_t g_EsHi[NFOREST * 8192];       // B1 [n][k-words] per forest
__device__ uint32_t g_EsLo[NFOREST * 8192];
__device__ uint32_t g_L1Hi[8192];                 // B2
__device__ uint32_t g_L1Lo[8192];
__device__ uint32_t g_L2Hi[1024];                 // B3 (16 rows x 64 words)
__device__ uint32_t g_L2Lo[1024];

// ---------------- helpers ----------------------------------------------------
__device__ __forceinline__ uint32_t pack_bf16(float a, float b) {
    __nv_bfloat16 ha = __float2bfloat16(a), hb = __float2bfloat16(b);
    return (uint32_t)__bfloat16_as_ushort(ha)
         | ((uint32_t)__bfloat16_as_ushort(hb) << 16);
}
__device__ __forceinline__ void split2(float a, float b,
                                       uint32_t& hi, uint32_t& lo) {
    __nv_bfloat16 ha = __float2bfloat16(a), hb = __float2bfloat16(b);
    float ra = a - __bfloat162float(ha);
    float rb = b - __bfloat162float(hb);
    hi = (uint32_t)__bfloat16_as_ushort(ha)
       | ((uint32_t)__bfloat16_as_ushort(hb) << 16);
    lo = pack_bf16(ra, rb);
}
__device__ __forceinline__ void mma_bf16(float* c,
    uint32_t a0, uint32_t a1, uint32_t a2, uint32_t a3,
    uint32_t b0, uint32_t b1) {
    asm volatile(
        "mma.sync.aligned.m16n8k16.row.col.f32.bf16.bf16.f32 "
        "{%0,%1,%2,%3},{%4,%5,%6,%7},{%8,%9},{%0,%1,%2,%3};"
        : "+f"(c[0]), "+f"(c[1]), "+f"(c[2]), "+f"(c[3])
        : "r"(a0), "r"(a1), "r"(a2), "r"(a3), "r"(b0), "r"(b1));
}
__device__ __forceinline__ float fast_sigmoid(float x) {
    float th;
    asm("tanh.approx.f32 %0, %1;" : "=f"(th) : "f"(x * 0.5f));
    return fmaf(0.5f, th, 0.5f);
}
__device__ __forceinline__ uint32_t smem_u32(const void* p) {
    uint32_t a;
    asm("{ .reg .u64 t; cvta.to.shared.u64 t, %1; cvt.u32.u64 %0, t; }"
        : "=r"(a) : "l"(p));
    return a;
}
__device__ __forceinline__ void cp16(uint32_t dst, const void* src) {
    asm volatile("cp.async.cg.shared.global [%0], [%1], 16;"
                 :: "r"(dst), "l"(src));
}
#define CP_COMMIT() asm volatile("cp.async.commit_group;" ::: "memory")
#define CP_WAIT(n)  asm volatile("cp.async.wait_group %0;" :: "n"(n) : "memory")

// ---------------------------------------------------------------------------
// Kernel 1: condition generation -> rODT scores w[b,g]
// ---------------------------------------------------------------------------
__global__ void cond_kernel(
    const float* __restrict__ x,    const float* __restrict__ w1,
    const float* __restrict__ b1,   const int*   __restrict__ perm,
    const float* __restrict__ gn1g, const float* __restrict__ gn1b,
    const float* __restrict__ w2a,  const float* __restrict__ b2a,
    const float* __restrict__ gn2g, const float* __restrict__ gn2b,
    const float* __restrict__ w2b,  const float* __restrict__ b2b)
{
    __shared__ float xs[NCOL];
    const int b = blockIdx.y;
    const int t = threadIdx.x;
    if (t < NCOL) xs[t] = x[b * NCOL + t];
    __syncthreads();

    const int g = blockIdx.x * 256 + t;
    const int4 p4 = ((const int4*)perm)[g];
    const int pv[4] = {p4.x, p4.y, p4.z, p4.w};
    float o[4];
#pragma unroll
    for (int i = 0; i < 4; i++) {
        const int p = pv[i];
        const int wi = (p & 63) * NCOND + (p >> 6);
        o[i] = fast_sigmoid(fmaf(xs[p & 63], w1[wi], b1[wi]));
    }
    float mu = 0.f, s2 = 0.f;
#pragma unroll
    for (int i = 0; i < 4; i++) { mu += o[i]; s2 += o[i] * o[i]; }
    mu *= 0.25f; s2 = s2 * 0.25f - mu * mu;
    const float rstd = rsqrtf(s2 + EPSF);
    const float4 g1  = ((const float4*)gn1g)[g];
    const float4 be1 = ((const float4*)gn1b)[g];
    float hn[4];
    hn[0] = (o[0] - mu) * rstd * g1.x + be1.x;
    hn[1] = (o[1] - mu) * rstd * g1.y + be1.y;
    hn[2] = (o[2] - mu) * rstd * g1.z + be1.z;
    hn[3] = (o[3] - mu) * rstd * g1.w + be1.w;

    const float4 bb2 = ((const float4*)b2a)[g];
    float h2[4] = {bb2.x, bb2.y, bb2.z, bb2.w};
#pragma unroll
    for (int i = 0; i < 4; i++) {
        const float4 wr = ((const float4*)w2a)[g * 4 + i];
        h2[0] = fmaf(hn[i], wr.x, h2[0]);
        h2[1] = fmaf(hn[i], wr.y, h2[1]);
        h2[2] = fmaf(hn[i], wr.z, h2[2]);
        h2[3] = fmaf(hn[i], wr.w, h2[3]);
    }
#pragma unroll
    for (int i = 0; i < 4; i++) h2[i] = fmaxf(h2[i], 0.f);
    float mu2 = 0.f, t2 = 0.f;
#pragma unroll
    for (int i = 0; i < 4; i++) { mu2 += h2[i]; t2 += h2[i] * h2[i]; }
    mu2 *= 0.25f; t2 = t2 * 0.25f - mu2 * mu2;
    const float rstd2 = rsqrtf(t2 + EPSF);
    const float4 g2  = ((const float4*)gn2g)[g];
    const float4 be2 = ((const float4*)gn2b)[g];
    const float4 wb  = ((const float4*)w2b)[g];
    float wv = b2b[g];
    wv = fmaf((h2[0] - mu2) * rstd2 * g2.x + be2.x, wb.x, wv);
    wv = fmaf((h2[1] - mu2) * rstd2 * g2.y + be2.y, wb.y, wv);
    wv = fmaf((h2[2] - mu2) * rstd2 * g2.z + be2.z, wb.z, wv);
    wv = fmaf((h2[3] - mu2) * rstd2 * g2.w + be2.w, wb.w, wv);
    g_W[b * NRODT + g] = wv;
}

// ---------------------------------------------------------------------------
// rowmax: warp per batch row
// ---------------------------------------------------------------------------
__global__ void rowmax_kernel()
{
    const int b = blockIdx.x * 8 + (threadIdx.x >> 5);
    const int lane = threadIdx.x & 31;
    const float4* p = (const float4*)(g_W + b * NRODT);
    float m = -1e30f;
#pragma unroll
    for (int j = 0; j < 8; j++) {
        const float4 v = p[lane + j * 32];
        m = fmaxf(m, fmaxf(fmaxf(v.x, v.y), fmaxf(v.z, v.w)));
    }
#pragma unroll
    for (int o = 16; o > 0; o >>= 1)
        m = fmaxf(m, __shfl_xor_sync(0xffffffffu, m, o));
    if (lane == 0) g_rmax[b] = m;
}

// fused exp + transpose: g_EWT[g][b] = exp(g_W[b][g] - rmax[b])
__global__ void expT_kernel()
{
    __shared__ float tile[32][33];
    const int bx = blockIdx.x * 32, by = blockIdx.y * 32;
    const int tx = threadIdx.x, ty = threadIdx.y;   // 32 x 8
#pragma unroll
    for (int j = 0; j < 32; j += 8) {
        const int b = by + ty + j;
        tile[ty + j][tx] = __expf(g_W[b * NRODT + bx + tx] - g_rmax[b]);
    }
    __syncthreads();
#pragma unroll
    for (int j = 0; j < 32; j += 8)
        g_EWT[(bx + ty + j) * BATCH + by + tx] = tile[tx][ty + j];
}

// ---------------------------------------------------------------------------
// Prep: split B operands into hi/lo bf16 word tiles ([n][64 words])
// ---------------------------------------------------------------------------
__global__ void prep_es(const float* __restrict__ E, const int* __restrict__ swr)
{
    __shared__ int idx[NEST];
    const int f = blockIdx.x;
    const int t = threadIdx.x;            // row n = hidden channel
    idx[t] = swr[f * NEST + t];
    __syncthreads();
    uint32_t* hiP = g_EsHi + f * 8192 + t * 64;
    uint32_t* loP = g_EsLo + f * 8192 + t * 64;
    const int w0 = blockIdx.y * 8;
#pragma unroll
    for (int w = w0; w < w0 + 8; w++) {
        const float v0 = E[(size_t)idx[2 * w]     * NHID + t];
        const float v1 = E[(size_t)idx[2 * w + 1] * NHID + t];
        uint32_t hi, lo;
        split2(v0, v1, hi, lo);
        hiP[w] = hi; loP[w] = lo;
    }
}
__global__ void prep_l1(const float* __restrict__ lin1w)
{
    const int t = threadIdx.x;            // row n = h2
    const int w0 = blockIdx.x * 8;
#pragma unroll
    for (int w = w0; w < w0 + 8; w++) {
        const float v0 = lin1w[(2 * w) * NHID + t];
        const float v1 = lin1w[(2 * w + 1) * NHID + t];
        uint32_t hi, lo;
        split2(v0, v1, hi, lo);
        g_L1Hi[t * 64 + w] = hi; g_L1Lo[t * 64 + w] = lo;
    }
}
__global__ void prep_l2(const float* __restrict__ lin2w)
{
    const int t = threadIdx.x;            // word index = k-pair
    const int n = blockIdx.x;
    const float v0 = (n < NCLASS) ? lin2w[(2 * t) * NCLASS + n] : 0.f;
    const float v1 = (n < NCLASS) ? lin2w[(2 * t + 1) * NCLASS + n] : 0.f;
    uint32_t hi, lo;
    split2(v0, v1, hi, lo);
    g_L2Hi[n * 64 + t] = hi; g_L2Lo[n * 64 + t] = lo;
}

// ---------------------------------------------------------------------------
// Kernel 2: HMMA forest kernel.  Block = (128-row tile, forest f), 8 warps.
// A fragments for GEMM2/GEMM3 live in registers (C->A fragment identity).
// B tiles streamed via cp.async: group1 = B1, group2 = B2+B3.
// ---------------------------------------------------------------------------
__global__ void __launch_bounds__(256, 1) forest_mma(
    const int*   __restrict__ swr,
    const float* __restrict__ ln1g, const float* __restrict__ ln1b,
    const float* __restrict__ lin1b,
    const float* __restrict__ ln2g, const float* __restrict__ ln2b,
    const float* __restrict__ lin2b)
{
    extern __shared__ __align__(16) uint32_t sw4[];
    __shared__ float Spart[2][128];
    __shared__ float pg1[128], pb1[128], plb[128], pg2[128], pb2[128];
    __shared__ float pl2b[16];
    __shared__ int idxs[NEST];

    const int t = threadIdx.x;
    const int f = blockIdx.y;
    const int b0 = blockIdx.x * 128;
    const int w = t >> 5, lane = t & 31, g = lane >> 2, tg = lane & 3;
    const int mbase = w * 16;

    // ---- async B tile copies ----
    {
        const uint32_t dbase = smem_u32(sw4);
        const uint4* s1h = (const uint4*)(g_EsHi + f * 8192);
        const uint4* s1l = (const uint4*)(g_EsLo + f * 8192);
        for (int i = t; i < 2048; i += 256) {
            const int n = i >> 4, q = i & 15;
            const uint32_t dd = (uint32_t)(n * 17 + q) * 16;
            cp16(dbase + W_B1H * 4 + dd, s1h + i);
            cp16(dbase + W_B1L * 4 + dd, s1l + i);
        }
        CP_COMMIT();
        const uint4* s2h = (const uint4*)g_L1Hi;
        const uint4* s2l = (const uint4*)g_L1Lo;
        for (int i = t; i < 2048; i += 256) {
            const int n = i >> 4, q = i & 15;
            const uint32_t dd = (uint32_t)(n * 17 + q) * 16;
            cp16(dbase + W_B2H * 4 + dd, s2h + i);
            cp16(dbase + W_B2L * 4 + dd, s2l + i);
        }
        const uint4* s3h = (const uint4*)g_L2Hi;
        const uint4* s3l = (const uint4*)g_L2Lo;
        if (t < 256) {
            const int i = t;
            const int n = i >> 4, q = i & 15;
            const uint32_t dd = (uint32_t)(n * 17 + q) * 16;
            cp16(dbase + W_B3H * 4 + dd, s3h + i);
            cp16(dbase + W_B3L * 4 + dd, s3l + i);
        }
        CP_COMMIT();
    }

    if (t < 128) {
        idxs[t] = swr[f * NEST + t];
        pg1[t] = ln1g[t]; pb1[t] = ln1b[t];
        plb[t] = lin1b[t];
        pg2[t] = ln2g[t]; pb2[t] = ln2b[t];
    }
    if (t < 16) pl2b[t] = (t < NCLASS) ? lin2b[t] : 0.f;
    __syncthreads();   // idxs visible for gather

    // ---- build A1 = gathered EW subset (split bf16), and row sums ----
    {
        const int m = t & 127, half = t >> 7;
        float s = 0.f;
        const float* ew = g_EWT + b0 + m;
        uint32_t* AH = sw4 + W_AHI + m * SW + half * 32;
        uint32_t* AL = sw4 + W_ALO + m * SW + half * 32;
#pragma unroll 4
        for (int j = 0; j < 32; j++) {
            const int e = half * 64 + 2 * j;
            const float a0 = ew[(size_t)idxs[e]     * BATCH];
            const float a1 = ew[(size_t)idxs[e + 1] * BATCH];
            s += a0 + a1;
            uint32_t hi, lo;
            split2(a0, a1, hi, lo);
            AH[j] = hi; AL[j] = lo;
        }
        Spart[half][m] = s;
    }
    CP_WAIT(1);        // B1 landed
    __syncthreads();   // A tile + Spart + B1 visible

    const int rowA = (mbase + g) * SW;
    const int rowB = (mbase + g + 8) * SW;

    // =============== GEMM1: D = A1 @ B1 (Es) ===============
    float C[16][4];
#pragma unroll
    for (int nt = 0; nt < 16; nt++)
#pragma unroll
        for (int j = 0; j < 4; j++) C[nt][j] = 0.f;

#pragma unroll
    for (int ks = 0; ks < 8; ks++) {
        const int kw = ks * 8 + tg;
        const uint32_t ah0 = sw4[W_AHI + rowA + kw];
        const uint32_t ah1 = sw4[W_AHI + rowB + kw];
        const uint32_t ah2 = sw4[W_AHI + rowA + kw + 4];
        const uint32_t ah3 = sw4[W_AHI + rowB + kw + 4];
        const uint32_t al0 = sw4[W_ALO + rowA + kw];
        const uint32_t al1 = sw4[W_ALO + rowB + kw];
        const uint32_t al2 = sw4[W_ALO + rowA + kw + 4];
        const uint32_t al3 = sw4[W_ALO + rowB + kw + 4];
#pragma unroll
        for (int nt = 0; nt < 16; nt++) {
            const int bn = W_B1H + (nt * 8 + g) * SW + kw;
            const uint32_t bh0 = sw4[bn], bh1 = sw4[bn + 4];
            const uint32_t bl0 = sw4[bn + 8704], bl1 = sw4[bn + 8704 + 4];
            mma_bf16(C[nt], ah0, ah1, ah2, ah3, bh0, bh1);
            mma_bf16(C[nt], ah0, ah1, ah2, ah3, bl0, bl1);
            mma_bf16(C[nt], al0, al1, al2, al3, bh0, bh1);
        }
    }

    // ---- epilogue 1: /S, LN1 -> A fragments in REGISTERS ----
    uint32_t Ah[16], Al[16], Bh[16], Bl[16];   // rows g / g+8, word nt
    {
        const float SA = Spart[0][mbase + g] + Spart[1][mbase + g];
        const float SB = Spart[0][mbase + g + 8] + Spart[1][mbase + g + 8];
        const float iA = 1.f / SA, iB = 1.f / SB;
        float sA = 0.f, qA = 0.f, sB = 0.f, qB = 0.f;
#pragma unroll
        for (int nt = 0; nt < 16; nt++) {
            C[nt][0] *= iA; C[nt][1] *= iA;
            C[nt][2] *= iB; C[nt][3] *= iB;
            sA += C[nt][0] + C[nt][1];
            qA += C[nt][0] * C[nt][0] + C[nt][1] * C[nt][1];
            sB += C[nt][2] + C[nt][3];
            qB += C[nt][2] * C[nt][2] + C[nt][3] * C[nt][3];
        }
#pragma unroll
        for (int o = 1; o <= 2; o <<= 1) {
            sA += __shfl_xor_sync(0xffffffffu, sA, o);
            qA += __shfl_xor_sync(0xffffffffu, qA, o);
            sB += __shfl_xor_sync(0xffffffffu, sB, o);
            qB += __shfl_xor_sync(0xffffffffu, qB, o);
        }
        const float mA = sA * (1.f / NHID);
        const float rA = rsqrtf(qA * (1.f / NHID) - mA * mA + EPSF);
        const float mB = sB * (1.f / NHID);
        const float rB = rsqrtf(qB * (1.f / NHID) - mB * mB + EPSF);
#pragma unroll
        for (int nt = 0; nt < 16; nt++) {
            const int n0 = nt * 8 + tg * 2, n1 = n0 + 1;
            const float zA0 = (C[nt][0] - mA) * rA * pg1[n0] + pb1[n0];
            const float zA1 = (C[nt][1] - mA) * rA * pg1[n1] + pb1[n1];
            const float zB0 = (C[nt][2] - mB) * rB * pg1[n0] + pb1[n0];
            const float zB1 = (C[nt][3] - mB) * rB * pg1[n1] + pb1[n1];
            split2(zA0, zA1, Ah[nt], Al[nt]);
            split2(zB0, zB1, Bh[nt], Bl[nt]);
        }
    }
    CP_WAIT(0);        // B2 + B3 landed
    __syncthreads();

    // =============== GEMM2: D = z1 @ lin1w (A from registers) ===============
#pragma unroll
    for (int nt = 0; nt < 16; nt++)
#pragma unroll
        for (int j = 0; j < 4; j++) C[nt][j] = 0.f;

#pragma unroll
    for (int ks = 0; ks < 8; ks++) {
        const int kw = ks * 8 + tg;
        const uint32_t ah0 = Ah[2 * ks],     ah1 = Bh[2 * ks];
        const uint32_t ah2 = Ah[2 * ks + 1], ah3 = Bh[2 * ks + 1];
        const uint32_t al0 = Al[2 * ks],     al1 = Bl[2 * ks];
        const uint32_t al2 = Al[2 * ks + 1], al3 = Bl[2 * ks + 1];
#pragma unroll
        for (int nt = 0; nt < 16; nt++) {
            const int bn = W_B2H + (nt * 8 + g) * SW + kw;
            const uint32_t bh0 = sw4[bn], bh1 = sw4[bn + 4];
            const uint32_t bl0 = sw4[bn + 8704], bl1 = sw4[bn + 8704 + 4];
            mma_bf16(C[nt], ah0, ah1, ah2, ah3, bh0, bh1);
            mma_bf16(C[nt], ah0, ah1, ah2, ah3, bl0, bl1);
            mma_bf16(C[nt], al0, al1, al2, al3, bh0, bh1);
        }
    }

    // ---- epilogue 2: +bias, ReLU, LN2 -> A fragments in registers ----
    {
        float sA = 0.f, qA = 0.f, sB = 0.f, qB = 0.f;
#pragma unroll
        for (int nt = 0; nt < 16; nt++) {
            const int n0 = nt * 8 + tg * 2, n1 = n0 + 1;
            C[nt][0] = fmaxf(C[nt][0] + plb[n0], 0.f);
            C[nt][1] = fmaxf(C[nt][1] + plb[n1], 0.f);
            C[nt][2] = fmaxf(C[nt][2] + plb[n0], 0.f);
            C[nt][3] = fmaxf(C[nt][3] + plb[n1], 0.f);
            sA += C[nt][0] + C[nt][1];
            qA += C[nt][0] * C[nt][0] + C[nt][1] * C[nt][1];
            sB += C[nt][2] + C[nt][3];
            qB += C[nt][2] * C[nt][2] + C[nt][3] * C[nt][3];
        }
#pragma unroll
        for (int o = 1; o <= 2; o <<= 1) {
            sA += __shfl_xor_sync(0xffffffffu, sA, o);
            qA += __shfl_xor_sync(0xffffffffu, qA, o);
            sB += __shfl_xor_sync(0xffffffffu, sB, o);
            qB += __shfl_xor_sync(0xffffffffu, qB, o);
        }
        const float mA = sA * (1.f / NHID);
        const float rA = rsqrtf(qA * (1.f / NHID) - mA * mA + EPSF);
        const float mB = sB * (1.f / NHID);
        const float rB = rsqrtf(qB * (1.f / NHID) - mB * mB + EPSF);
#pragma unroll
        for (int nt = 0; nt < 16; nt++) {
            const int n0 = nt * 8 + tg * 2, n1 = n0 + 1;
            const float zA0 = (C[nt][0] - mA) * rA * pg2[n0] + pb2[n0];
            const float zA1 = (C[nt][1] - mA) * rA * pg2[n1] + pb2[n1];
            const float zB0 = (C[nt][2] - mB) * rB * pg2[n0] + pb2[n0];
            const float zB1 = (C[nt][3] - mB) * rB * pg2[n1] + pb2[n1];
            split2(zA0, zA1, Ah[nt], Al[nt]);
            split2(zB0, zB1, Bh[nt], Bl[nt]);
        }
    }

    // =============== GEMM3: logits = z2 @ lin2w (N=16 padded) ===============
    float Y[2][4];
#pragma unroll
    for (int nt = 0; nt < 2; nt++)
#pragma unroll
        for (int j = 0; j < 4; j++) Y[nt][j] = 0.f;

#pragma unroll
    for (int ks = 0; ks < 8; ks++) {
        const int kw = ks * 8 + tg;
        const uint32_t ah0 = Ah[2 * ks],     ah1 = Bh[2 * ks];
        const uint32_t ah2 = Ah[2 * ks + 1], ah3 = Bh[2 * ks + 1];
        const uint32_t al0 = Al[2 * ks],     al1 = Bl[2 * ks];
        const uint32_t al2 = Al[2 * ks + 1], al3 = Bl[2 * ks + 1];
#pragma unroll
        for (int nt = 0; nt < 2; nt++) {
            const int bn = W_B3H + (nt * 8 + g) * SW + kw;
            const uint32_t bh0 = sw4[bn], bh1 = sw4[bn + 4];
            const uint32_t bl0 = sw4[bn + 1088], bl1 = sw4[bn + 1088 + 4];
            mma_bf16(Y[nt], ah0, ah1, ah2, ah3, bh0, bh1);
            mma_bf16(Y[nt], ah0, ah1, ah2, ah3, bl0, bl1);
            mma_bf16(Y[nt], al0, al1, al2, al3, bh0, bh1);
        }
    }

    // ---- write logits ----
    {
        float* yA = g_Y + ((size_t)f * BATCH + b0 + mbase + g) * NCLASS;
        float* yB = g_Y + ((size_t)f * BATCH + b0 + mbase + g + 8) * NCLASS;
#pragma unroll
        for (int nt = 0; nt < 2; nt++) {
            const int n0 = nt * 8 + tg * 2, n1 = n0 + 1;
            if (n0 < NCLASS) {
                yA[n0] = Y[nt][0] + pl2b[n0];
                yB[n0] = Y[nt][2] + pl2b[n0];
            }
            if (n1 < NCLASS) {
                yA[n1] = Y[nt][1] + pl2b[n1];
                yB[n1] = Y[nt][3] + pl2b[n1];
            }
        }
    }
}

// ---------------------------------------------------------------------------
// Kernel 3: mean over forests, 4-way f-split per block
// ---------------------------------------------------------------------------
__global__ void mean_kernel(float* __restrict__ out)
{
    __shared__ float part[4][64];
    const int t = threadIdx.x;
    const int i = blockIdx.x * 64 + (t & 63);
    const int fg = t >> 6;
    float s = 0.f;
#pragma unroll 5
    for (int f = fg * 25; f < fg * 25 + 25; f++)
        s += g_Y[(size_t)f * (BATCH * NCLASS) + i];
    part[fg][t & 63] = s;
    __syncthreads();
    if (t < 64)
        out[blockIdx.x * 64 + t] =
            (part[0][t] + part[1][t] + part[2][t] + part[3][t]) * (1.f / NFOREST);
}

// ---------------------------------------------------------------------------
extern "C" void kernel_launch(void* const* d_in, const int* in_sizes, int n_in,
                              void* d_out, int out_size)
{
    const float* x     = (const float*)d_in[0];
    const float* w1    = (const float*)d_in[1];
    const float* b1    = (const float*)d_in[2];
    const int*   perm  = (const int*)  d_in[3];
    const float* gn1g  = (const float*)d_in[4];
    const float* gn1b  = (const float*)d_in[5];
    const float* w2a   = (const float*)d_in[6];
    const float* b2a   = (const float*)d_in[7];
    const float* gn2g  = (const float*)d_in[8];
    const float* gn2b  = (const float*)d_in[9];
    const float* w2b   = (const float*)d_in[10];
    const float* b2b   = (const float*)d_in[11];
    const float* E     = (const float*)d_in[12];
    const int*   swr   = (const int*)  d_in[13];
    const float* ln1g  = (const float*)d_in[14];
    const float* ln1b  = (const float*)d_in[15];
    const float* lin1w = (const float*)d_in[16];
    const float* lin1b = (const float*)d_in[17];
    const float* ln2g  = (const float*)d_in[18];
    const float* ln2b  = (const float*)d_in[19];
    const float* lin2w = (const float*)d_in[20];
    const float* lin2b = (const float*)d_in[21];

    const int dyn_smem = SMEM_WORDS * 4;   // 217,600 B
    cudaFuncSetAttribute(forest_mma,
                         cudaFuncAttributeMaxDynamicSharedMemorySize, dyn_smem);

    cond_kernel<<<dim3(NRODT / 256, BATCH), 256>>>(
        x, w1, b1, perm, gn1g, gn1b, w2a, b2a, gn2g, gn2b, w2b, b2b);
    rowmax_kernel<<<BATCH / 8, 256>>>();
    expT_kernel<<<dim3(NRODT / 32, BATCH / 32), dim3(32, 8)>>>();
    prep_es<<<dim3(NFOREST, 8), 128>>>(E, swr);
    prep_l1<<<8, 128>>>(lin1w);
    prep_l2<<<16, 64>>>(lin2w);

    forest_mma<<<dim3(BATCH / 128, NFOREST), 256, dyn_smem>>>(
        swr, ln1g, ln1b, lin1b, ln2g, ln2b, lin2b);

    mean_kernel<<<BATCH * NCLASS / 64, 256>>>((float*)d_out);
}